// round 4
// baseline (speedup 1.0000x reference)
#include <cuda_runtime.h>
#include <math.h>

#define NQ    12
#define DIM   4096
#define KS    6
#define BATCH 256
#define SEQ   128
#define DEMB  512
#define NCLS  8

// scratch for encoder -> quantum handoff (no allocation allowed)
__device__ float g_x[BATCH * NQ];

__device__ __forceinline__ int physaddr(int i) { return i ^ ((i >> 4) & 0xF); }

// CNOT-ring composition: bits 0..10 = suffix parity, bit 11 = parity(bits 0..10)
__device__ __forceinline__ int permT(int x) {
    int p = x ^ (x >> 1);
    p ^= p >> 2;
    p ^= p >> 4;
    p ^= p >> 8;
    return (p & 0x7FF) | (((p ^ (x >> 11)) & 1) << 11);
}

// ---- packed f32x2 helpers (Blackwell FFMA2) ----
union F2U { float2 f; unsigned long long u; };
__device__ __forceinline__ float2 ffma2(float2 a, float2 b, float2 c) {
    F2U A, B, C, R; A.f = a; B.f = b; C.f = c;
    asm("fma.rn.f32x2 %0, %1, %2, %3;" : "=l"(R.u) : "l"(A.u), "l"(B.u), "l"(C.u));
    return R.f;
}
__device__ __forceinline__ float2 fmul2(float2 a, float2 b) {
    F2U A, B, R; A.f = a; B.f = b;
    asm("mul.rn.f32x2 %0, %1, %2;" : "=l"(R.u) : "l"(A.u), "l"(B.u));
    return R.f;
}

// ---------------------------------------------------------------------------
// Encoder: embed -> masked mean pool -> tanh(linear)*pi, fused.
// ---------------------------------------------------------------------------
__global__ void __launch_bounds__(SEQ) encoder_kernel(
    const int* __restrict__ ids, const int* __restrict__ mask,
    const float* __restrict__ emb, const float* __restrict__ pw,
    const float* __restrict__ pb)
{
    int b = blockIdx.x, t = threadIdx.x;
    __shared__ int   sid[SEQ];
    __shared__ float smk[SEQ];
    __shared__ float red[4][NQ];
    sid[t] = ids[b * SEQ + t];
    smk[t] = (float)mask[b * SEQ + t];
    __syncthreads();

    float a0 = 0.f, a1 = 0.f, a2 = 0.f, a3 = 0.f, cnt = 0.f;
    for (int s = 0; s < SEQ; s++) {
        float m = smk[s];
        cnt += m;
        if (m != 0.f) {
            const float4 e = __ldg((const float4*)(emb + (size_t)sid[s] * DEMB + t * 4));
            a0 += m * e.x; a1 += m * e.y; a2 += m * e.z; a3 += m * e.w;
        }
    }
    float inv = 1.0f / fmaxf(cnt, 1.0f);

    float z[NQ];
#pragma unroll
    for (int q = 0; q < NQ; q++) {
        const float4 w = __ldg((const float4*)(pw + q * DEMB + t * 4));
        z[q] = a0 * w.x + a1 * w.y + a2 * w.z + a3 * w.w;
    }
#pragma unroll
    for (int q = 0; q < NQ; q++) {
#pragma unroll
        for (int off = 16; off; off >>= 1)
            z[q] += __shfl_down_sync(0xffffffffu, z[q], off);
    }
    int w = t >> 5, l = t & 31;
    if (l == 0) {
#pragma unroll
        for (int q = 0; q < NQ; q++) red[w][q] = z[q];
    }
    __syncthreads();
    if (t < NQ) {
        float s = red[0][t] + red[1][t] + red[2][t] + red[3][t];
        g_x[b * NQ + t] = tanhf(s * inv + pb[t]) * 3.14159265358979f;
    }
}

// 4 fused single-qubit gates on a 16-amp register group; level k2 -> wire wtop-k2.
// Packed f32x2: each amp (re,im) is one 64-bit operand; complex 2x2 butterfly =
// 8 packed FMA-pipe ops per pair (vs 16 scalar FFMA) + 2 half-swaps on ALU pipe.
__device__ __forceinline__ void apply4(float2 v[16], const float2* gm, int wtop) {
#pragma unroll
    for (int k2 = 0; k2 < 4; k2++) {
        float2 m00 = gm[(wtop - k2) * 4 + 0];
        float2 m01 = gm[(wtop - k2) * 4 + 1];
        float2 m10 = gm[(wtop - k2) * 4 + 2];
        float2 m11 = gm[(wtop - k2) * 4 + 3];
        // splat / sign-folded constants
        float2 a00 = make_float2(m00.x, m00.x), b00 = make_float2(-m00.y, m00.y);
        float2 a01 = make_float2(m01.x, m01.x), b01 = make_float2(-m01.y, m01.y);
        float2 a10 = make_float2(m10.x, m10.x), b10 = make_float2(-m10.y, m10.y);
        float2 a11 = make_float2(m11.x, m11.x), b11 = make_float2(-m11.y, m11.y);
        int s = 1 << k2;
#pragma unroll
        for (int i = 0; i < 16; i++) {
            if (i & s) continue;
            float2 p0 = v[i], p1 = v[i | s];
            float2 p0s = make_float2(p0.y, p0.x);
            float2 p1s = make_float2(p1.y, p1.x);
            v[i]     = ffma2(a00, p0, ffma2(b00, p0s, ffma2(a01, p1, fmul2(b01, p1s))));
            v[i | s] = ffma2(a10, p0, ffma2(b10, p0s, ffma2(a11, p1, fmul2(b11, p1s))));
        }
    }
}

// ---------------------------------------------------------------------------
// Quantum simulator: one CTA per sample, 2 CTAs/SM, state in SMEM (swizzled).
// ---------------------------------------------------------------------------
__global__ void __launch_bounds__(256, 2) quantum_kernel(
    const float* __restrict__ theta, const float* __restrict__ hw,
    const float* __restrict__ hb, float* __restrict__ out)
{
    __shared__ float2 st[DIM];      // 32 KB state, swizzled addressing
    __shared__ float2 gm[NQ][4];    // fused gate matrices for current step
    __shared__ float  ro[KS][NQ];   // readouts (wire-indexed)
    __shared__ float  wred[8][NQ];
    __shared__ float  xs[NQ];

    int b = blockIdx.x, t = threadIdx.x;
    if (t < NQ) xs[t] = g_x[b * NQ + t];

    // init |0...0>
#pragma unroll
    for (int g = 0; g < 16; g++) {
        int idx = t + (g << 8);
        st[physaddr(idx)] = make_float2(idx == 0 ? 1.f : 0.f, 0.f);
    }

    for (int k = 0; k < KS; k++) {
        __syncthreads();
        if (t < NQ) {
            // fused G = Rot(phi,theta,omega) * RY(x) for wire t
            float cy, sy;  sincosf(0.5f * xs[t], &sy, &cy);
            const float* th = theta + (k * NQ + t) * 3;
            float phi = th[0], tha = th[1], om = th[2];
            float ct, stt; sincosf(0.5f * tha, &stt, &ct);
            float ca, sa;  sincosf(0.5f * (phi + om), &sa, &ca); // ep = (ca,-sa)
            float cb, sb;  sincosf(0.5f * (phi - om), &sb, &cb); // em = (cb, sb)
            float r00 = ct * cy, r01 = ct * sy, r10 = stt * cy, r11 = stt * sy;
            gm[t][0] = make_float2( ca * r00 - cb * r11, -sa * r00 - sb * r11);
            gm[t][1] = make_float2(-ca * r01 - cb * r10,  sa * r01 - sb * r10);
            gm[t][2] = make_float2( cb * r10 + ca * r01, -sb * r10 + sa * r01);
            gm[t][3] = make_float2(-cb * r11 + ca * r00,  sb * r11 + sa * r00);
        }
        __syncthreads();

        float2 v[16];

        // --- sweep A: bits 8..11 (wires 3..0) ---
#pragma unroll
        for (int g = 0; g < 16; g++) v[g] = st[physaddr(t | (g << 8))];
        apply4(v, (const float2*)gm, 3);
#pragma unroll
        for (int g = 0; g < 16; g++) st[physaddr(t | (g << 8))] = v[g];
        __syncthreads();

        // --- sweep B: bits 4..7 (wires 7..4) ---
        int baseB = (t & 15) | ((t >> 4) << 8);
#pragma unroll
        for (int g = 0; g < 16; g++) v[g] = st[physaddr(baseB | (g << 4))];
        apply4(v, (const float2*)gm, 7);
#pragma unroll
        for (int g = 0; g < 16; g++) st[physaddr(baseB | (g << 4))] = v[g];
        __syncthreads();

        // --- sweep C: bits 0..3 (wires 11..8) + CNOT ring perm + readout ---
        int baseC = t << 4;
#pragma unroll
        for (int g = 0; g < 16; g++) v[g] = st[physaddr(baseC | g)];
        __syncthreads();   // all loads complete before permuted scatter
        apply4(v, (const float2*)gm, 11);

        float zb[NQ];
#pragma unroll
        for (int bb = 0; bb < NQ; bb++) zb[bb] = 0.f;
        float ptot = 0.f;
        int ybase = permT(baseC);
#pragma unroll
        for (int g = 0; g < 16; g++) {
            int y = permT(baseC | g);
            st[physaddr(y)] = v[g];
            float p = v[g].x * v[g].x + v[g].y * v[g].y;
            ptot += p;
            // within a group only bits {0,1,2,3,11} of y vary
            zb[0]  += ((y      ) & 1) ? -p : p;
            zb[1]  += ((y >> 1 ) & 1) ? -p : p;
            zb[2]  += ((y >> 2 ) & 1) ? -p : p;
            zb[3]  += ((y >> 3 ) & 1) ? -p : p;
            zb[11] += ((y >> 11) & 1) ? -p : p;
        }
#pragma unroll
        for (int bb = 4; bb < 11; bb++)
            zb[bb] = ((ybase >> bb) & 1) ? -ptot : ptot;

        // block reduce 12 accumulators
#pragma unroll
        for (int bb = 0; bb < NQ; bb++) {
#pragma unroll
            for (int off = 16; off; off >>= 1)
                zb[bb] += __shfl_down_sync(0xffffffffu, zb[bb], off);
        }
        int w = t >> 5, l = t & 31;
        if (l == 0) {
#pragma unroll
            for (int bb = 0; bb < NQ; bb++) wred[w][bb] = zb[bb];
        }
        __syncthreads();
        if (t < NQ) {
            float s = 0.f;
#pragma unroll
            for (int w2 = 0; w2 < 8; w2++) s += wred[w2][11 - t]; // wire t = bit 11-t
            ro[k][t] = s;
        }
    }
    __syncthreads();

    // heads + outputs.  Layout: step_logits[6,256,8] | step_readouts[6,256,12] | final[256,8]
    if (t < KS * NCLS) {
        int k = t >> 3, c = t & 7;
        float s = hb[c];
#pragma unroll
        for (int j = 0; j < NQ; j++) s += hw[c * NQ + j] * ro[k][j];
        out[(k * BATCH + b) * NCLS + c] = s;
        if (k == KS - 1)
            out[KS * BATCH * NCLS + KS * BATCH * NQ + b * NCLS + c] = s;
    }
    if (t >= 64 && t < 64 + KS * NQ) {
        int u = t - 64;
        int k = u / NQ, j = u % NQ;
        out[KS * BATCH * NCLS + (k * BATCH + b) * NQ + j] = ro[k][j];
    }
}

extern "C" void kernel_launch(void* const* d_in, const int* in_sizes, int n_in,
                              void* d_out, int out_size)
{
    const int*   ids   = (const int*)d_in[0];
    const int*   mask  = (const int*)d_in[1];
    const float* emb   = (const float*)d_in[2];
    const float* pw    = (const float*)d_in[3];
    const float* pb    = (const float*)d_in[4];
    const float* theta = (const float*)d_in[5];
    const float* hw    = (const float*)d_in[6];
    const float* hb    = (const float*)d_in[7];
    float* out = (float*)d_out;

    encoder_kernel<<<BATCH, SEQ>>>(ids, mask, emb, pw, pb);
    quantum_kernel<<<BATCH, 256>>>(theta, hw, hb, out);
}

// round 5
// speedup vs baseline: 1.0687x; 1.0687x over previous
#include <cuda_runtime.h>
#include <math.h>

#define NQ    12
#define DIM   4096
#define KS    6
#define BATCH 256
#define SEQ   128
#define DEMB  512
#define NCLS  8
#define NT    512

__device__ __forceinline__ int physaddr(int i) { return i ^ ((i >> 4) & 0xF); }

// CNOT-ring composition: bits 0..10 = suffix parity, bit 11 = parity(bits 0..10)
__device__ __forceinline__ int permT(int x) {
    int p = x ^ (x >> 1);
    p ^= p >> 2;
    p ^= p >> 4;
    p ^= p >> 8;
    return (p & 0x7FF) | (((p ^ (x >> 11)) & 1) << 11);
}

// 3 fused single-qubit gates on an 8-amp register group; level k2 -> wire wtop-k2
__device__ __forceinline__ void apply3(float2 v[8], const float2 (*gm)[4], int wtop) {
#pragma unroll
    for (int k2 = 0; k2 < 3; k2++) {
        float2 m00 = gm[wtop - k2][0];
        float2 m01 = gm[wtop - k2][1];
        float2 m10 = gm[wtop - k2][2];
        float2 m11 = gm[wtop - k2][3];
        int s = 1 << k2;
#pragma unroll
        for (int i = 0; i < 8; i++) {
            if (i & s) continue;
            float2 p0 = v[i], p1 = v[i | s];
            float2 n0, n1;
            n0.x = m00.x * p0.x - m00.y * p0.y + m01.x * p1.x - m01.y * p1.y;
            n0.y = m00.x * p0.y + m00.y * p0.x + m01.x * p1.y + m01.y * p1.x;
            n1.x = m10.x * p0.x - m10.y * p0.y + m11.x * p1.x - m11.y * p1.y;
            n1.y = m10.x * p0.y + m10.y * p0.x + m11.x * p1.y + m11.y * p1.x;
            v[i] = n0;
            v[i | s] = n1;
        }
    }
}

// ---------------------------------------------------------------------------
// Fully fused, 1 sample per CTA, 512 threads, grid=256 (one wave @ 2 CTA/SM).
// ---------------------------------------------------------------------------
__global__ void __launch_bounds__(NT, 2) fused_kernel(
    const int* __restrict__ ids, const int* __restrict__ mask,
    const float* __restrict__ emb, const float* __restrict__ pw,
    const float* __restrict__ pb, const float* __restrict__ theta,
    const float* __restrict__ hw, const float* __restrict__ hb,
    float* __restrict__ out)
{
    __shared__ float2 st[DIM];      // 32 KB state (swizzled addressing)
    __shared__ float2 gm[NQ][4];
    __shared__ float  ro[KS][NQ];
    __shared__ float  wred[16][NQ];
    __shared__ float  xs[NQ];

    int b = blockIdx.x, t = threadIdx.x;

    // ===================== encoder phase (scratch aliases st) =================
    int*   sid  = (int*)st;                      // [SEQ]
    float* smk  = (float*)st + SEQ;              // [SEQ]
    float* ered = (float*)st + 2 * SEQ;          // [16][13]
    if (t < SEQ) {
        sid[t] = ids[b * SEQ + t];
        smk[t] = (float)mask[b * SEQ + t];
    }
    __syncthreads();

    {
        int d = t & 127, sh = t >> 7;            // dim-chunk, seq-quarter
        float a0 = 0.f, a1 = 0.f, a2 = 0.f, a3 = 0.f, cnt = 0.f;
        for (int s = sh * 32; s < sh * 32 + 32; s++) {
            float m = smk[s];
            cnt += m;
            if (m != 0.f) {
                const float4 e = __ldg((const float4*)(emb + (size_t)sid[s] * DEMB + d * 4));
                a0 += m * e.x; a1 += m * e.y; a2 += m * e.z; a3 += m * e.w;
            }
        }
        float z[NQ + 1];
#pragma unroll
        for (int q = 0; q < NQ; q++) {
            const float4 w = __ldg((const float4*)(pw + q * DEMB + d * 4));
            z[q] = a0 * w.x + a1 * w.y + a2 * w.z + a3 * w.w;
        }
        z[NQ] = cnt;
#pragma unroll
        for (int q = 0; q <= NQ; q++) {
#pragma unroll
            for (int off = 16; off; off >>= 1)
                z[q] += __shfl_down_sync(0xffffffffu, z[q], off);
        }
        __syncthreads();                         // sid/smk reads done
        int w = t >> 5, l = t & 31;
        if (l == 0) {
#pragma unroll
            for (int q = 0; q <= NQ; q++) ered[w * 13 + q] = z[q];
        }
        __syncthreads();
        if (t < NQ) {
            float s = 0.f, c = 0.f;
#pragma unroll
            for (int w2 = 0; w2 < 16; w2++) {
                s += ered[w2 * 13 + t];
                c += ered[w2 * 13 + NQ];
            }
            float inv = 1.0f / fmaxf(c * (1.0f / 128.0f), 1.0f);
            xs[t] = tanhf(s * inv + pb[t]) * 3.14159265358979f;
        }
    }
    __syncthreads();

    // ===================== quantum phase =====================
    // init |0...0>
#pragma unroll
    for (int g = 0; g < 8; g++) {
        int idx = t | (g << 9);
        st[physaddr(idx)] = make_float2(idx == 0 ? 1.f : 0.f, 0.f);
    }

    for (int k = 0; k < KS; k++) {
        __syncthreads();
        if (t < NQ) {
            // fused G = Rot(phi,theta,omega) * RY(x) for wire t
            float cy, sy;  sincosf(0.5f * xs[t], &sy, &cy);
            const float* th = theta + (k * NQ + t) * 3;
            float phi = th[0], tha = th[1], om = th[2];
            float ct, stt; sincosf(0.5f * tha, &stt, &ct);
            float ca, sa;  sincosf(0.5f * (phi + om), &sa, &ca); // ep = (ca,-sa)
            float cb, sb;  sincosf(0.5f * (phi - om), &sb, &cb); // em = (cb, sb)
            float r00 = ct * cy, r01 = ct * sy, r10 = stt * cy, r11 = stt * sy;
            gm[t][0] = make_float2( ca * r00 - cb * r11, -sa * r00 - sb * r11);
            gm[t][1] = make_float2(-ca * r01 - cb * r10,  sa * r01 - sb * r10);
            gm[t][2] = make_float2( cb * r10 + ca * r01, -sb * r10 + sa * r01);
            gm[t][3] = make_float2(-cb * r11 + ca * r00,  sb * r11 + sa * r00);
        }
        __syncthreads();

        float2 v[8];

        // --- sweep A: bits 9..11 (wires 2..0) ---
#pragma unroll
        for (int g = 0; g < 8; g++) v[g] = st[physaddr(t | (g << 9))];
        apply3(v, gm, 2);
#pragma unroll
        for (int g = 0; g < 8; g++) st[physaddr(t | (g << 9))] = v[g];
        __syncthreads();

        // --- sweep B: bits 6..8 (wires 5..3) ---
        int baseB = (t & 63) | ((t >> 6) << 9);
#pragma unroll
        for (int g = 0; g < 8; g++) v[g] = st[physaddr(baseB | (g << 6))];
        apply3(v, gm, 5);
#pragma unroll
        for (int g = 0; g < 8; g++) st[physaddr(baseB | (g << 6))] = v[g];
        __syncthreads();

        // --- sweep C: bits 3..5 (wires 8..6) ---
        int baseC = (t & 7) | ((t >> 3) << 6);
#pragma unroll
        for (int g = 0; g < 8; g++) v[g] = st[physaddr(baseC | (g << 3))];
        apply3(v, gm, 8);
#pragma unroll
        for (int g = 0; g < 8; g++) st[physaddr(baseC | (g << 3))] = v[g];
        __syncthreads();

        // --- sweep D: bits 0..2 (wires 11..9) + CNOT ring perm + readout ---
        int baseD = t << 3;
#pragma unroll
        for (int g = 0; g < 8; g++) v[g] = st[physaddr(baseD | g)];
        __syncthreads();   // all loads complete before permuted scatter
        apply3(v, gm, 11);

        float zb[NQ];
#pragma unroll
        for (int bb = 0; bb < NQ; bb++) zb[bb] = 0.f;
        float ptot = 0.f;
        int ybase = permT(baseD);
#pragma unroll
        for (int g = 0; g < 8; g++) {
            int y = permT(baseD | g);
            st[physaddr(y)] = v[g];
            float p = v[g].x * v[g].x + v[g].y * v[g].y;
            ptot += p;
            // within a group only bits {0,1,2,11} of y vary
            zb[0]  += ((y      ) & 1) ? -p : p;
            zb[1]  += ((y >> 1 ) & 1) ? -p : p;
            zb[2]  += ((y >> 2 ) & 1) ? -p : p;
            zb[11] += ((y >> 11) & 1) ? -p : p;
        }
#pragma unroll
        for (int bb = 3; bb < 11; bb++)
            zb[bb] = ((ybase >> bb) & 1) ? -ptot : ptot;

        // reduce 12 accumulators across 16 warps
#pragma unroll
        for (int bb = 0; bb < NQ; bb++) {
#pragma unroll
            for (int off = 16; off; off >>= 1)
                zb[bb] += __shfl_down_sync(0xffffffffu, zb[bb], off);
        }
        int w = t >> 5, l = t & 31;
        if (l == 0) {
#pragma unroll
            for (int bb = 0; bb < NQ; bb++) wred[w][bb] = zb[bb];
        }
        __syncthreads();
        if (t < NQ) {
            float s = 0.f;
#pragma unroll
            for (int w2 = 0; w2 < 16; w2++) s += wred[w2][11 - t]; // wire t = bit 11-t
            ro[k][t] = s;
        }
    }
    __syncthreads();

    // heads + outputs. Layout: step_logits[6,256,8] | step_readouts[6,256,12] | final[256,8]
    if (t < KS * NCLS) {
        int k = t >> 3, c = t & 7;
        float s = hb[c];
#pragma unroll
        for (int j = 0; j < NQ; j++) s += hw[c * NQ + j] * ro[k][j];
        out[(k * BATCH + b) * NCLS + c] = s;
        if (k == KS - 1)
            out[KS * BATCH * NCLS + KS * BATCH * NQ + b * NCLS + c] = s;
    }
    if (t >= 64 && t < 64 + KS * NQ) {
        int u = t - 64;
        int k = u / NQ, j = u % NQ;
        out[KS * BATCH * NCLS + (k * BATCH + b) * NQ + j] = ro[k][j];
    }
}

extern "C" void kernel_launch(void* const* d_in, const int* in_sizes, int n_in,
                              void* d_out, int out_size)
{
    const int*   ids   = (const int*)d_in[0];
    const int*   mask  = (const int*)d_in[1];
    const float* emb   = (const float*)d_in[2];
    const float* pw    = (const float*)d_in[3];
    const float* pb    = (const float*)d_in[4];
    const float* theta = (const float*)d_in[5];
    const float* hw    = (const float*)d_in[6];
    const float* hb    = (const float*)d_in[7];
    float* out = (float*)d_out;

    fused_kernel<<<BATCH, NT>>>(ids, mask, emb, pw, pb, theta, hw, hb, out);
}

// round 6
// speedup vs baseline: 1.2512x; 1.1708x over previous
#include <cuda_runtime.h>
#include <math.h>

#define NQ    12
#define DIM   4096
#define KS    6
#define BATCH 256
#define SEQ   128
#define DEMB  512
#define NCLS  8

// scratch for encoder -> quantum handoff (no allocation allowed)
__device__ float g_x[BATCH * NQ];

__device__ __forceinline__ int physaddr(int i) { return i ^ ((i >> 4) & 0xF); }

// CNOT-ring composition: bits 0..10 = suffix parity, bit 11 = parity(bits 0..10)
__device__ __forceinline__ int permT(int x) {
    int p = x ^ (x >> 1);
    p ^= p >> 2;
    p ^= p >> 4;
    p ^= p >> 8;
    return (p & 0x7FF) | (((p ^ (x >> 11)) & 1) << 11);
}

__device__ __forceinline__ float2 cmul(float2 a, float2 b) {
    return make_float2(a.x * b.x - a.y * b.y, a.x * b.y + a.y * b.x);
}

// ---------------------------------------------------------------------------
// Encoder: embed -> masked mean pool -> tanh(linear)*pi. 256 thr/CTA.
// ---------------------------------------------------------------------------
__global__ void __launch_bounds__(256) encoder_kernel(
    const int* __restrict__ ids, const int* __restrict__ mask,
    const float* __restrict__ emb, const float* __restrict__ pw,
    const float* __restrict__ pb)
{
    int b = blockIdx.x, t = threadIdx.x;
    __shared__ int   sid[SEQ];
    __shared__ float smk[SEQ];
    __shared__ float ered[8][13];
    if (t < SEQ) {
        sid[t] = ids[b * SEQ + t];
        smk[t] = (float)mask[b * SEQ + t];
    }
    __syncthreads();

    int d = t & 127, sh = t >> 7;   // dim-chunk, seq-half
    float a0 = 0.f, a1 = 0.f, a2 = 0.f, a3 = 0.f, cnt = 0.f;
#pragma unroll 4
    for (int s = sh * 64; s < sh * 64 + 64; s++) {
        float m = smk[s];
        cnt += m;
        const float4 e = __ldg((const float4*)(emb + (size_t)sid[s] * DEMB + d * 4));
        a0 += m * e.x; a1 += m * e.y; a2 += m * e.z; a3 += m * e.w;
    }

    float z[NQ + 1];
#pragma unroll
    for (int q = 0; q < NQ; q++) {
        const float4 w = __ldg((const float4*)(pw + q * DEMB + d * 4));
        z[q] = a0 * w.x + a1 * w.y + a2 * w.z + a3 * w.w;
    }
    z[NQ] = cnt;
#pragma unroll
    for (int q = 0; q <= NQ; q++) {
#pragma unroll
        for (int off = 16; off; off >>= 1)
            z[q] += __shfl_down_sync(0xffffffffu, z[q], off);
    }
    int w = t >> 5, l = t & 31;
    if (l == 0) {
#pragma unroll
        for (int q = 0; q <= NQ; q++) ered[w][q] = z[q];
    }
    __syncthreads();
    if (t < NQ) {
        float s = 0.f, c = 0.f;
#pragma unroll
        for (int w2 = 0; w2 < 8; w2++) { s += ered[w2][t]; c += ered[w2][NQ]; }
        float inv = 1.0f / fmaxf(c * (1.0f / 128.0f), 1.0f);
        g_x[b * NQ + t] = tanhf(s * inv + pb[t]) * 3.14159265358979f;
    }
}

// 4 fused single-qubit gates on a 16-amp register group; level k2 -> wire wtop-k2
__device__ __forceinline__ void apply4(float2 v[16], const float2 (*gm)[4], int wtop) {
#pragma unroll
    for (int k2 = 0; k2 < 4; k2++) {
        float2 m00 = gm[wtop - k2][0];
        float2 m01 = gm[wtop - k2][1];
        float2 m10 = gm[wtop - k2][2];
        float2 m11 = gm[wtop - k2][3];
        int s = 1 << k2;
#pragma unroll
        for (int i = 0; i < 16; i++) {
            if (i & s) continue;
            float2 p0 = v[i], p1 = v[i | s];
            float2 n0, n1;
            n0.x = m00.x * p0.x - m00.y * p0.y + m01.x * p1.x - m01.y * p1.y;
            n0.y = m00.x * p0.y + m00.y * p0.x + m01.x * p1.y + m01.y * p1.x;
            n1.x = m10.x * p0.x - m10.y * p0.y + m11.x * p1.x - m11.y * p1.y;
            n1.y = m10.x * p0.y + m10.y * p0.x + m11.x * p1.y + m11.y * p1.x;
            v[i] = n0;
            v[i | s] = n1;
        }
    }
}

// CNOT-ring permuted scatter + Z readout for a sweep-C register group
// (thread t owns idx = t*16+g). Writes ro_k[0..11]. Contains __syncthreads.
__device__ __forceinline__ void perm_scatter_readout(
    float2 v[16], float2* st, float (*wred)[NQ], float* ro_k, int t)
{
    float zb[NQ];
#pragma unroll
    for (int bb = 0; bb < NQ; bb++) zb[bb] = 0.f;
    float ptot = 0.f;
    int baseC = t << 4;
    int ybase = permT(baseC);
#pragma unroll
    for (int g = 0; g < 16; g++) {
        int y = permT(baseC | g);
        st[physaddr(y)] = v[g];
        float p = v[g].x * v[g].x + v[g].y * v[g].y;
        ptot += p;
        // within a group only bits {0,1,2,3,11} of y vary
        zb[0]  += ((y      ) & 1) ? -p : p;
        zb[1]  += ((y >> 1 ) & 1) ? -p : p;
        zb[2]  += ((y >> 2 ) & 1) ? -p : p;
        zb[3]  += ((y >> 3 ) & 1) ? -p : p;
        zb[11] += ((y >> 11) & 1) ? -p : p;
    }
#pragma unroll
    for (int bb = 4; bb < 11; bb++)
        zb[bb] = ((ybase >> bb) & 1) ? -ptot : ptot;

#pragma unroll
    for (int bb = 0; bb < NQ; bb++) {
#pragma unroll
        for (int off = 16; off; off >>= 1)
            zb[bb] += __shfl_down_sync(0xffffffffu, zb[bb], off);
    }
    int w = t >> 5, l = t & 31;
    if (l == 0) {
#pragma unroll
        for (int bb = 0; bb < NQ; bb++) wred[w][bb] = zb[bb];
    }
    __syncthreads();
    if (t < NQ) {
        float s = 0.f;
#pragma unroll
        for (int w2 = 0; w2 < 8; w2++) s += wred[w2][11 - t]; // wire t = bit 11-t
        ro_k[t] = s;
    }
}

// ---------------------------------------------------------------------------
// Quantum simulator: one CTA per sample, 2 CTAs/SM, state in SMEM (swizzled).
// Step 1 computed analytically from the product state; steps 2..6 butterflies.
// ---------------------------------------------------------------------------
__global__ void __launch_bounds__(256, 2) quantum_kernel(
    const float* __restrict__ theta, const float* __restrict__ hw,
    const float* __restrict__ hb, float* __restrict__ out)
{
    __shared__ float2 st[DIM];            // 32 KB state, swizzled addressing
    __shared__ float2 gmall[KS][NQ][4];   // all fused gate matrices
    __shared__ float2 plo[16];            // step-1 low-bit partial products
    __shared__ float  ro[KS][NQ];
    __shared__ float  wred[8][NQ];
    __shared__ float  xs[NQ];

    int b = blockIdx.x, t = threadIdx.x;
    if (t < NQ) xs[t] = g_x[b * NQ + t];
    __syncthreads();

    // --- precompute ALL fused gates G = Rot(phi,theta,omega)*RY(x), 72 in parallel
    if (t < KS * NQ) {
        int k = t / NQ, q = t % NQ;
        float cy, sy;  sincosf(0.5f * xs[q], &sy, &cy);
        const float* th = theta + (k * NQ + q) * 3;
        float phi = th[0], tha = th[1], om = th[2];
        float ct, stt; sincosf(0.5f * tha, &stt, &ct);
        float ca, sa;  sincosf(0.5f * (phi + om), &sa, &ca); // ep = (ca,-sa)
        float cb, sb;  sincosf(0.5f * (phi - om), &sb, &cb); // em = (cb, sb)
        float r00 = ct * cy, r01 = ct * sy, r10 = stt * cy, r11 = stt * sy;
        gmall[k][q][0] = make_float2( ca * r00 - cb * r11, -sa * r00 - sb * r11);
        gmall[k][q][1] = make_float2(-ca * r01 - cb * r10,  sa * r01 - sb * r10);
        gmall[k][q][2] = make_float2( cb * r10 + ca * r01, -sb * r10 + sa * r01);
        gmall[k][q][3] = make_float2(-cb * r11 + ca * r00,  sb * r11 + sa * r00);
    }
    // step-1 low-bit table: idx bits 0..3 -> wires 11..8; col0 = (m00, m10)
    __syncthreads();
    if (t < 16) {
        float2 p = ((t     ) & 1) ? gmall[0][11][2] : gmall[0][11][0];
        p = cmul(p, ((t >> 1) & 1) ? gmall[0][10][2] : gmall[0][10][0]);
        p = cmul(p, ((t >> 2) & 1) ? gmall[0][ 9][2] : gmall[0][ 9][0]);
        p = cmul(p, ((t >> 3) & 1) ? gmall[0][ 8][2] : gmall[0][ 8][0]);
        plo[t] = p;
    }
    __syncthreads();

    // ===== step 1 (analytic product state; amp(idx) = P_hi(t) * plo[g]) =====
    {
        // idx = t*16+g; t's bit j = idx bit 4+j -> wire 7-j
        float2 pt = (t & 1) ? gmall[0][7][2] : gmall[0][7][0];
#pragma unroll
        for (int j = 1; j < 8; j++)
            pt = cmul(pt, ((t >> j) & 1) ? gmall[0][7 - j][2] : gmall[0][7 - j][0]);
        float2 v[16];
#pragma unroll
        for (int g = 0; g < 16; g++) v[g] = cmul(pt, plo[g]);
        perm_scatter_readout(v, st, wred, ro[0], t);
    }

    // ===== steps 2..6: three butterfly sweeps =====
    for (int k = 1; k < KS; k++) {
        __syncthreads();                 // prior scatter complete
        const float2 (*gm)[4] = gmall[k];
        float2 v[16];

        // --- sweep A: bits 8..11 (wires 3..0) ---
#pragma unroll
        for (int g = 0; g < 16; g++) v[g] = st[physaddr(t | (g << 8))];
        apply4(v, gm, 3);
#pragma unroll
        for (int g = 0; g < 16; g++) st[physaddr(t | (g << 8))] = v[g];
        __syncthreads();

        // --- sweep B: bits 4..7 (wires 7..4) ---
        int baseB = (t & 15) | ((t >> 4) << 8);
#pragma unroll
        for (int g = 0; g < 16; g++) v[g] = st[physaddr(baseB | (g << 4))];
        apply4(v, gm, 7);
#pragma unroll
        for (int g = 0; g < 16; g++) st[physaddr(baseB | (g << 4))] = v[g];
        __syncthreads();

        // --- sweep C: bits 0..3 (wires 11..8) + CNOT ring perm + readout ---
        int baseC = t << 4;
#pragma unroll
        for (int g = 0; g < 16; g++) v[g] = st[physaddr(baseC | g)];
        __syncthreads();                 // all loads complete before scatter
        apply4(v, gm, 11);
        perm_scatter_readout(v, st, wred, ro[k], t);
    }
    __syncthreads();

    // heads + outputs. Layout: step_logits[6,256,8] | step_readouts[6,256,12] | final[256,8]
    if (t < KS * NCLS) {
        int k = t >> 3, c = t & 7;
        float s = hb[c];
#pragma unroll
        for (int j = 0; j < NQ; j++) s += hw[c * NQ + j] * ro[k][j];
        out[(k * BATCH + b) * NCLS + c] = s;
        if (k == KS - 1)
            out[KS * BATCH * NCLS + KS * BATCH * NQ + b * NCLS + c] = s;
    }
    if (t >= 64 && t < 64 + KS * NQ) {
        int u = t - 64;
        int k = u / NQ, j = u % NQ;
        out[KS * BATCH * NCLS + (k * BATCH + b) * NQ + j] = ro[k][j];
    }
}

extern "C" void kernel_launch(void* const* d_in, const int* in_sizes, int n_in,
                              void* d_out, int out_size)
{
    const int*   ids   = (const int*)d_in[0];
    const int*   mask  = (const int*)d_in[1];
    const float* emb   = (const float*)d_in[2];
    const float* pw    = (const float*)d_in[3];
    const float* pb    = (const float*)d_in[4];
    const float* theta = (const float*)d_in[5];
    const float* hw    = (const float*)d_in[6];
    const float* hb    = (const float*)d_in[7];
    float* out = (float*)d_out;

    encoder_kernel<<<BATCH, 256>>>(ids, mask, emb, pw, pb);
    quantum_kernel<<<BATCH, 256>>>(theta, hw, hb, out);
}

// round 7
// speedup vs baseline: 1.4015x; 1.1201x over previous
#include <cuda_runtime.h>
#include <math.h>

#define NQ    12
#define DIM   4096
#define KS    6
#define BATCH 256
#define SEQ   128
#define DEMB  512
#define NCLS  8

// scratch for encoder -> quantum handoff (no allocation allowed)
__device__ float g_x[BATCH * NQ];

// swizzle: XOR low nibble with next nibble (GF(2)-linear)
__device__ __host__ constexpr int swzc(int i) { return i ^ ((i >> 4) & 0xF); }

// CNOT-ring composition: bits 0..10 = suffix parity, bit 11 = parity(bits 0..10)
// (GF(2)-linear)
__device__ __host__ constexpr int permTc(int x) {
    int p = x ^ (x >> 1);
    p ^= p >> 2;
    p ^= p >> 4;
    p ^= p >> 8;
    return (p & 0x7FF) | (((p ^ (x >> 11)) & 1) << 11);
}

__device__ __forceinline__ float2 cmul(float2 a, float2 b) {
    return make_float2(a.x * b.x - a.y * b.y, a.x * b.y + a.y * b.x);
}

// ---------------------------------------------------------------------------
// Encoder: embed -> masked mean pool -> tanh(linear)*pi. 256 thr/CTA.
// ---------------------------------------------------------------------------
__global__ void __launch_bounds__(256) encoder_kernel(
    const int* __restrict__ ids, const int* __restrict__ mask,
    const float* __restrict__ emb, const float* __restrict__ pw,
    const float* __restrict__ pb)
{
    int b = blockIdx.x, t = threadIdx.x;
    __shared__ int   sid[SEQ];
    __shared__ float smk[SEQ];
    __shared__ float ered[8][13];
    if (t < SEQ) {
        sid[t] = ids[b * SEQ + t];
        smk[t] = (float)mask[b * SEQ + t];
    }
    __syncthreads();

    int d = t & 127, sh = t >> 7;   // dim-chunk, seq-half
    float a0 = 0.f, a1 = 0.f, a2 = 0.f, a3 = 0.f, cnt = 0.f;
#pragma unroll 4
    for (int s = sh * 64; s < sh * 64 + 64; s++) {
        float m = smk[s];
        cnt += m;
        const float4 e = __ldg((const float4*)(emb + (size_t)sid[s] * DEMB + d * 4));
        a0 += m * e.x; a1 += m * e.y; a2 += m * e.z; a3 += m * e.w;
    }

    float z[NQ + 1];
#pragma unroll
    for (int q = 0; q < NQ; q++) {
        const float4 w = __ldg((const float4*)(pw + q * DEMB + d * 4));
        z[q] = a0 * w.x + a1 * w.y + a2 * w.z + a3 * w.w;
    }
    z[NQ] = cnt;
#pragma unroll
    for (int q = 0; q <= NQ; q++) {
#pragma unroll
        for (int off = 16; off; off >>= 1)
            z[q] += __shfl_down_sync(0xffffffffu, z[q], off);
    }
    int w = t >> 5, l = t & 31;
    if (l == 0) {
#pragma unroll
        for (int q = 0; q <= NQ; q++) ered[w][q] = z[q];
    }
    __syncthreads();
    if (t < NQ) {
        float s = 0.f, c = 0.f;
#pragma unroll
        for (int w2 = 0; w2 < 8; w2++) { s += ered[w2][t]; c += ered[w2][NQ]; }
        float inv = 1.0f / fmaxf(c * (1.0f / 128.0f), 1.0f);
        g_x[b * NQ + t] = tanhf(s * inv + pb[t]) * 3.14159265358979f;
    }
}

// 4 fused single-qubit gates on a 16-amp register group; level k2 -> wire wtop-k2
__device__ __forceinline__ void apply4(float2 v[16], const float2 (*gm)[4], int wtop) {
#pragma unroll
    for (int k2 = 0; k2 < 4; k2++) {
        float2 m00 = gm[wtop - k2][0];
        float2 m01 = gm[wtop - k2][1];
        float2 m10 = gm[wtop - k2][2];
        float2 m11 = gm[wtop - k2][3];
        int s = 1 << k2;
#pragma unroll
        for (int i = 0; i < 16; i++) {
            if (i & s) continue;
            float2 p0 = v[i], p1 = v[i | s];
            float2 n0, n1;
            n0.x = m00.x * p0.x - m00.y * p0.y + m01.x * p1.x - m01.y * p1.y;
            n0.y = m00.x * p0.y + m00.y * p0.x + m01.x * p1.y + m01.y * p1.x;
            n1.x = m10.x * p0.x - m10.y * p0.y + m11.x * p1.x - m11.y * p1.y;
            n1.y = m10.x * p0.y + m10.y * p0.x + m11.x * p1.y + m11.y * p1.x;
            v[i] = n0;
            v[i | s] = n1;
        }
    }
}

// CNOT-ring permuted scatter + Z readout for a sweep-C register group
// (thread t owns idx = t*16+g). All addresses decompose as (per-thread base)
// XOR (compile-time constant) by GF(2)-linearity of permT and swz.
// Readout signs for bits 0..3,11 are compile-time per g. Contains __syncthreads.
__device__ __forceinline__ void perm_scatter_readout(
    float2 v[16], float2* st, float (*wred)[NQ], float* ro_k, int t)
{
    const int ybase = permTc(t << 4);          // once per thread
    const int sybase = swzc(ybase);            // swizzled scatter base

    float acc0 = 0.f, acc1 = 0.f, acc2 = 0.f, acc3 = 0.f, acc11 = 0.f, ptot = 0.f;
#pragma unroll
    for (int g = 0; g < 16; g++) {
        constexpr_scatter:;
        const int PT = permTc(g);              // compile-time
        const int SPT = swzc(PT);              // compile-time
        st[sybase ^ SPT] = v[g];
        float p = v[g].x * v[g].x + v[g].y * v[g].y;
        ptot += p;
        acc0  += (PT & 1)        ? -p : p;     // folds to FADD/FSUB
        acc1  += ((PT >> 1) & 1) ? -p : p;
        acc2  += ((PT >> 2) & 1) ? -p : p;
        acc3  += ((PT >> 3) & 1) ? -p : p;
        acc11 += ((PT >> 11) & 1)? -p : p;
    }

    float zb[NQ];
    zb[0]  = (ybase & 1)         ? -acc0  : acc0;
    zb[1]  = ((ybase >> 1) & 1)  ? -acc1  : acc1;
    zb[2]  = ((ybase >> 2) & 1)  ? -acc2  : acc2;
    zb[3]  = ((ybase >> 3) & 1)  ? -acc3  : acc3;
    zb[11] = ((ybase >> 11) & 1) ? -acc11 : acc11;
#pragma unroll
    for (int bb = 4; bb < 11; bb++)
        zb[bb] = ((ybase >> bb) & 1) ? -ptot : ptot;

#pragma unroll
    for (int bb = 0; bb < NQ; bb++) {
#pragma unroll
        for (int off = 16; off; off >>= 1)
            zb[bb] += __shfl_down_sync(0xffffffffu, zb[bb], off);
    }
    int w = t >> 5, l = t & 31;
    if (l == 0) {
#pragma unroll
        for (int bb = 0; bb < NQ; bb++) wred[w][bb] = zb[bb];
    }
    __syncthreads();
    if (t < NQ) {
        float s = 0.f;
#pragma unroll
        for (int w2 = 0; w2 < 8; w2++) s += wred[w2][11 - t]; // wire t = bit 11-t
        ro_k[t] = s;
    }
}

// ---------------------------------------------------------------------------
// Quantum simulator: one CTA per sample, 2 CTAs/SM, state in SMEM (swizzled).
// Step 1 analytic (product state); steps 2..6 butterflies with XOR-const
// addressing throughout.
// ---------------------------------------------------------------------------
__global__ void __launch_bounds__(256, 2) quantum_kernel(
    const float* __restrict__ theta, const float* __restrict__ hw,
    const float* __restrict__ hb, float* __restrict__ out)
{
    __shared__ float2 st[DIM];            // 32 KB state, swizzled addressing
    __shared__ float2 gmall[KS][NQ][4];   // all fused gate matrices
    __shared__ float2 plo[16];            // step-1 low-bit partial products
    __shared__ float  ro[KS][NQ];
    __shared__ float  wred[8][NQ];
    __shared__ float  xs[NQ];

    int b = blockIdx.x, t = threadIdx.x;
    if (t < NQ) xs[t] = g_x[b * NQ + t];
    __syncthreads();

    // --- precompute ALL fused gates G = Rot(phi,theta,omega)*RY(x), 72 in parallel
    if (t < KS * NQ) {
        int k = t / NQ, q = t % NQ;
        float cy, sy;  sincosf(0.5f * xs[q], &sy, &cy);
        const float* th = theta + (k * NQ + q) * 3;
        float phi = th[0], tha = th[1], om = th[2];
        float ct, stt; sincosf(0.5f * tha, &stt, &ct);
        float ca, sa;  sincosf(0.5f * (phi + om), &sa, &ca); // ep = (ca,-sa)
        float cb, sb;  sincosf(0.5f * (phi - om), &sb, &cb); // em = (cb, sb)
        float r00 = ct * cy, r01 = ct * sy, r10 = stt * cy, r11 = stt * sy;
        gmall[k][q][0] = make_float2( ca * r00 - cb * r11, -sa * r00 - sb * r11);
        gmall[k][q][1] = make_float2(-ca * r01 - cb * r10,  sa * r01 - sb * r10);
        gmall[k][q][2] = make_float2( cb * r10 + ca * r01, -sb * r10 + sa * r01);
        gmall[k][q][3] = make_float2(-cb * r11 + ca * r00,  sb * r11 + sa * r00);
    }
    // step-1 low-bit table: idx bits 0..3 -> wires 11..8; col0 = (m00, m10)
    __syncthreads();
    if (t < 16) {
        float2 p = ((t     ) & 1) ? gmall[0][11][2] : gmall[0][11][0];
        p = cmul(p, ((t >> 1) & 1) ? gmall[0][10][2] : gmall[0][10][0]);
        p = cmul(p, ((t >> 2) & 1) ? gmall[0][ 9][2] : gmall[0][ 9][0]);
        p = cmul(p, ((t >> 3) & 1) ? gmall[0][ 8][2] : gmall[0][ 8][0]);
        plo[t] = p;
    }
    __syncthreads();

    // ===== step 1 (analytic product state; amp(idx) = P_hi(t) * plo[g]) =====
    {
        float2 pt = (t & 1) ? gmall[0][7][2] : gmall[0][7][0];
#pragma unroll
        for (int j = 1; j < 8; j++)
            pt = cmul(pt, ((t >> j) & 1) ? gmall[0][7 - j][2] : gmall[0][7 - j][0]);
        float2 v[16];
#pragma unroll
        for (int g = 0; g < 16; g++) v[g] = cmul(pt, plo[g]);
        perm_scatter_readout(v, st, wred, ro[0], t);
    }

    // per-thread swizzled bases (step-invariant, computed once)
    const int swzA  = swzc(t);                       // sweep A: + (g<<8)
    const int baseB = (t & 15) | ((t >> 4) << 8);    // sweep B: ^ ((g<<4)|g)
    const int swzC  = (t << 4) | (t & 15);           // sweep C: ^ g

    // ===== steps 2..6: three butterfly sweeps =====
    for (int k = 1; k < KS; k++) {
        __syncthreads();                 // prior scatter complete
        const float2 (*gm)[4] = gmall[k];
        float2 v[16];

        // --- sweep A: bits 8..11 (wires 3..0), affine addresses ---
#pragma unroll
        for (int g = 0; g < 16; g++) v[g] = st[swzA + (g << 8)];
        apply4(v, gm, 3);
#pragma unroll
        for (int g = 0; g < 16; g++) st[swzA + (g << 8)] = v[g];
        __syncthreads();

        // --- sweep B: bits 4..7 (wires 7..4), XOR-const addresses ---
#pragma unroll
        for (int g = 0; g < 16; g++) v[g] = st[baseB ^ ((g << 4) | g)];
        apply4(v, gm, 7);
#pragma unroll
        for (int g = 0; g < 16; g++) st[baseB ^ ((g << 4) | g)] = v[g];
        __syncthreads();

        // --- sweep C: bits 0..3 (wires 11..8) + CNOT ring perm + readout ---
#pragma unroll
        for (int g = 0; g < 16; g++) v[g] = st[swzC ^ g];
        __syncthreads();                 // all loads complete before scatter
        apply4(v, gm, 11);
        perm_scatter_readout(v, st, wred, ro[k], t);
    }
    __syncthreads();

    // heads + outputs. Layout: step_logits[6,256,8] | step_readouts[6,256,12] | final[256,8]
    if (t < KS * NCLS) {
        int k = t >> 3, c = t & 7;
        float s = hb[c];
#pragma unroll
        for (int j = 0; j < NQ; j++) s += hw[c * NQ + j] * ro[k][j];
        out[(k * BATCH + b) * NCLS + c] = s;
        if (k == KS - 1)
            out[KS * BATCH * NCLS + KS * BATCH * NQ + b * NCLS + c] = s;
    }
    if (t >= 64 && t < 64 + KS * NQ) {
        int u = t - 64;
        int k = u / NQ, j = u % NQ;
        out[KS * BATCH * NCLS + (k * BATCH + b) * NQ + j] = ro[k][j];
    }
}

extern "C" void kernel_launch(void* const* d_in, const int* in_sizes, int n_in,
                              void* d_out, int out_size)
{
    const int*   ids   = (const int*)d_in[0];
    const int*   mask  = (const int*)d_in[1];
    const float* emb   = (const float*)d_in[2];
    const float* pw    = (const float*)d_in[3];
    const float* pb    = (const float*)d_in[4];
    const float* theta = (const float*)d_in[5];
    const float* hw    = (const float*)d_in[6];
    const float* hb    = (const float*)d_in[7];
    float* out = (float*)d_out;

    encoder_kernel<<<BATCH, 256>>>(ids, mask, emb, pw, pb);
    quantum_kernel<<<BATCH, 256>>>(theta, hw, hb, out);
}

// round 8
// speedup vs baseline: 1.6304x; 1.1633x over previous
#include <cuda_runtime.h>
#include <math.h>

#define NQ    12
#define DIM   4096
#define KS    6
#define BATCH 256
#define SEQ   128
#define DEMB  512
#define NCLS  8

// scratch for encoder -> quantum handoff (no allocation allowed)
__device__ float g_x[BATCH * NQ];

// swizzle: XOR low nibble with next nibble (GF(2)-linear)
__device__ __host__ constexpr int swzc(int i) { return i ^ ((i >> 4) & 0xF); }

// CNOT-ring composition: bits 0..10 = suffix parity, bit 11 = parity(bits 0..10)
__device__ __host__ constexpr int permTc(int x) {
    int p = x ^ (x >> 1);
    p ^= p >> 2;
    p ^= p >> 4;
    p ^= p >> 8;
    return (p & 0x7FF) | (((p ^ (x >> 11)) & 1) << 11);
}

__device__ __forceinline__ float2 cmul(float2 a, float2 b) {
    return make_float2(a.x * b.x - a.y * b.y, a.x * b.y + a.y * b.x);
}

// ---------------------------------------------------------------------------
// Encoder: embed -> masked mean pool -> tanh(linear)*pi. 256 thr/CTA.
// ---------------------------------------------------------------------------
__global__ void __launch_bounds__(256) encoder_kernel(
    const int* __restrict__ ids, const int* __restrict__ mask,
    const float* __restrict__ emb, const float* __restrict__ pw,
    const float* __restrict__ pb)
{
    int b = blockIdx.x, t = threadIdx.x;
    __shared__ int   sid[SEQ];
    __shared__ float smk[SEQ];
    __shared__ float ered[8][13];
    if (t < SEQ) {
        sid[t] = ids[b * SEQ + t];
        smk[t] = (float)mask[b * SEQ + t];
    }
    __syncthreads();

    int d = t & 127, sh = t >> 7;   // dim-chunk, seq-half
    float a0 = 0.f, a1 = 0.f, a2 = 0.f, a3 = 0.f, cnt = 0.f;
#pragma unroll 4
    for (int s = sh * 64; s < sh * 64 + 64; s++) {
        float m = smk[s];
        cnt += m;
        const float4 e = __ldg((const float4*)(emb + (size_t)sid[s] * DEMB + d * 4));
        a0 += m * e.x; a1 += m * e.y; a2 += m * e.z; a3 += m * e.w;
    }

    float z[NQ + 1];
#pragma unroll
    for (int q = 0; q < NQ; q++) {
        const float4 w = __ldg((const float4*)(pw + q * DEMB + d * 4));
        z[q] = a0 * w.x + a1 * w.y + a2 * w.z + a3 * w.w;
    }
    z[NQ] = cnt;
#pragma unroll
    for (int q = 0; q <= NQ; q++) {
#pragma unroll
        for (int off = 16; off; off >>= 1)
            z[q] += __shfl_down_sync(0xffffffffu, z[q], off);
    }
    int w = t >> 5, l = t & 31;
    if (l == 0) {
#pragma unroll
        for (int q = 0; q <= NQ; q++) ered[w][q] = z[q];
    }
    __syncthreads();
    if (t < NQ) {
        float s = 0.f, c = 0.f;
#pragma unroll
        for (int w2 = 0; w2 < 8; w2++) { s += ered[w2][t]; c += ered[w2][NQ]; }
        float inv = 1.0f / fmaxf(c * (1.0f / 128.0f), 1.0f);
        g_x[b * NQ + t] = tanhf(s * inv + pb[t]) * 3.14159265358979f;
    }
}

// CNOT-ring permuted scatter (optional) + Z readout for a sweep-C register
// group (thread t owns idx = t*16+g). Diagonal phases never change |amp|^2,
// so this is valid on the decomposed state. Contains __syncthreads.
template <bool STORE>
__device__ __forceinline__ void perm_scatter_readout(
    float2 v[16], float2* st, float (*wred)[NQ], float* ro_k, int t)
{
    const int ybase = permTc(t << 4);          // once per thread
    const int sybase = swzc(ybase);            // swizzled scatter base

    float acc0 = 0.f, acc1 = 0.f, acc2 = 0.f, acc3 = 0.f, acc11 = 0.f, ptot = 0.f;
#pragma unroll
    for (int g = 0; g < 16; g++) {
        const int PT = permTc(g);              // compile-time
        const int SPT = swzc(PT);              // compile-time
        if (STORE) st[sybase ^ SPT] = v[g];
        float p = v[g].x * v[g].x + v[g].y * v[g].y;
        ptot += p;
        acc0  += (PT & 1)        ? -p : p;     // folds to FADD/FSUB
        acc1  += ((PT >> 1) & 1) ? -p : p;
        acc2  += ((PT >> 2) & 1) ? -p : p;
        acc3  += ((PT >> 3) & 1) ? -p : p;
        acc11 += ((PT >> 11) & 1)? -p : p;
    }

    float zb[NQ];
    zb[0]  = (ybase & 1)         ? -acc0  : acc0;
    zb[1]  = ((ybase >> 1) & 1)  ? -acc1  : acc1;
    zb[2]  = ((ybase >> 2) & 1)  ? -acc2  : acc2;
    zb[3]  = ((ybase >> 3) & 1)  ? -acc3  : acc3;
    zb[11] = ((ybase >> 11) & 1) ? -acc11 : acc11;
#pragma unroll
    for (int bb = 4; bb < 11; bb++)
        zb[bb] = ((ybase >> bb) & 1) ? -ptot : ptot;

#pragma unroll
    for (int bb = 0; bb < NQ; bb++) {
#pragma unroll
        for (int off = 16; off; off >>= 1)
            zb[bb] += __shfl_down_sync(0xffffffffu, zb[bb], off);
    }
    int w = t >> 5, l = t & 31;
    if (l == 0) {
#pragma unroll
        for (int bb = 0; bb < NQ; bb++) wred[w][bb] = zb[bb];
    }
    __syncthreads();
    if (t < NQ) {
        float s = 0.f;
#pragma unroll
        for (int w2 = 0; w2 < 8; w2++) s += wred[w2][11 - t]; // wire t = bit 11-t
        ro_k[t] = s;
    }
}

// ---------------------------------------------------------------------------
// Quantum simulator: one CTA per sample, 2 CTAs/SM, state in SMEM (swizzled).
// Each fused gate decomposed as diag(1,wpost) * [[c,-s],[s,c]] * diag(1,wpre)
// (global phase dropped; only |psi|^2 feeds outputs). Sweep B is pure real;
// pre-diag folds into sweep A gates + per-thread dfix scalar; post-diag folds
// into sweep C gates + dfixp scalar (skipped entirely on the last step).
// ---------------------------------------------------------------------------
__global__ void __launch_bounds__(256, 2) quantum_kernel(
    const float* __restrict__ theta, const float* __restrict__ hw,
    const float* __restrict__ hb, float* __restrict__ out)
{
    __shared__ float2 st[DIM];            // 32 KB state, swizzled addressing
    __shared__ float2 gp[KS][NQ][4];      // [0]=(c,s) [1]=wpre [2]=wpost [3]=s*wpost
    __shared__ float2 plo[16];            // step-1 low-bit partial products
    __shared__ float  ro[KS][NQ];
    __shared__ float  wred[8][NQ];
    __shared__ float  xs[NQ];

    int b = blockIdx.x, t = threadIdx.x;
    if (t < NQ) xs[t] = g_x[b * NQ + t];
    __syncthreads();

    // --- precompute ALL fused gates and their D*R*D decompositions, 72 threads
    if (t < KS * NQ) {
        int k = t / NQ, q = t % NQ;
        float cy, sy;  sincosf(0.5f * xs[q], &sy, &cy);
        const float* th = theta + (k * NQ + q) * 3;
        float phi = th[0], tha = th[1], om = th[2];
        float ct, stt; sincosf(0.5f * tha, &stt, &ct);
        float ca, sa;  sincosf(0.5f * (phi + om), &sa, &ca); // ep = (ca,-sa)
        float cb, sb;  sincosf(0.5f * (phi - om), &sb, &cb); // em = (cb, sb)
        float r00 = ct * cy, r01 = ct * sy, r10 = stt * cy, r11 = stt * sy;
        float2 G00 = make_float2( ca * r00 - cb * r11, -sa * r00 - sb * r11);
        float2 G01 = make_float2(-ca * r01 - cb * r10,  sa * r01 - sb * r10);
        float2 G10 = make_float2( cb * r10 + ca * r01, -sb * r10 + sa * r01);

        float c = sqrtf(G00.x * G00.x + G00.y * G00.y);
        float s = sqrtf(G10.x * G10.x + G10.y * G10.y);
        float2 cj = make_float2(G00.x, -G00.y);
        float2 wpre = cmul(make_float2(-G01.x, -G01.y), cj);
        float n1 = wpre.x * wpre.x + wpre.y * wpre.y;
        if (n1 > 1e-24f) { float r = rsqrtf(n1); wpre.x *= r; wpre.y *= r; }
        else wpre = make_float2(1.f, 0.f);
        float2 wpost = cmul(G10, cj);
        float n2 = wpost.x * wpost.x + wpost.y * wpost.y;
        if (n2 > 1e-24f) { float r = rsqrtf(n2); wpost.x *= r; wpost.y *= r; }
        else wpost = make_float2(1.f, 0.f);

        gp[k][q][0] = make_float2(c, s);
        gp[k][q][1] = wpre;
        gp[k][q][2] = wpost;
        gp[k][q][3] = make_float2(s * wpost.x, s * wpost.y);  // col0 bit-1 entry
    }
    // step-1 low-bit table: idx bits 0..3 -> wires 11..8; col0 = (c, s*wpost)
    __syncthreads();
    if (t < 16) {
        float2 p = ((t     ) & 1) ? gp[0][11][3] : make_float2(gp[0][11][0].x, 0.f);
        p = cmul(p, ((t >> 1) & 1) ? gp[0][10][3] : make_float2(gp[0][10][0].x, 0.f));
        p = cmul(p, ((t >> 2) & 1) ? gp[0][ 9][3] : make_float2(gp[0][ 9][0].x, 0.f));
        p = cmul(p, ((t >> 3) & 1) ? gp[0][ 8][3] : make_float2(gp[0][ 8][0].x, 0.f));
        plo[t] = p;
    }
    __syncthreads();

    // ===== step 1 (analytic product state; amp(idx) = P_hi(t) * plo[g]) =====
    {
        float2 pt = (t & 1) ? gp[0][7][3] : make_float2(gp[0][7][0].x, 0.f);
#pragma unroll
        for (int j = 1; j < 8; j++)
            pt = cmul(pt, ((t >> j) & 1) ? gp[0][7 - j][3]
                                         : make_float2(gp[0][7 - j][0].x, 0.f));
        float2 v[16];
#pragma unroll
        for (int g = 0; g < 16; g++) v[g] = cmul(pt, plo[g]);
        perm_scatter_readout<true>(v, st, wred, ro[0], t);
    }

    // per-thread swizzled bases (step-invariant)
    const int swzA  = swzc(t);                       // sweep A: + (g<<8)
    const int baseB = (t & 15) | ((t >> 4) << 8);    // sweep B: ^ ((g<<4)|g)
    const int swzC  = (t << 4) | (t & 15);           // sweep C: ^ g

    // ===== steps 2..6 =====
    for (int k = 1; k < KS; k++) {
        __syncthreads();                 // prior scatter complete
        const float2 (*gm)[4] = gp[k];
        float2 v[16];

        // --- sweep A: bits 8..11 (wires 3..0), pre-diag folded: R * diag(1,wpre)
#pragma unroll
        for (int g = 0; g < 16; g++) v[g] = st[swzA + (g << 8)];
#pragma unroll
        for (int k2 = 0; k2 < 4; k2++) {
            int w = 3 - k2;
            float c = gm[w][0].x, s = gm[w][0].y;
            float2 wp = gm[w][1];
            float2 sw = make_float2(s * wp.x, s * wp.y);
            float2 cw = make_float2(c * wp.x, c * wp.y);
            int sft = 1 << k2;
#pragma unroll
            for (int i = 0; i < 16; i++) {
                if (i & sft) continue;
                float2 p0 = v[i], p1 = v[i | sft];
                float ax = sw.x * p1.x - sw.y * p1.y;
                float ay = sw.x * p1.y + sw.y * p1.x;
                float bx = cw.x * p1.x - cw.y * p1.y;
                float by = cw.x * p1.y + cw.y * p1.x;
                v[i]       = make_float2(c * p0.x - ax, c * p0.y - ay);
                v[i | sft] = make_float2(s * p0.x + bx, s * p0.y + by);
            }
        }
        // pre-diag fixed bits 0..7 (wires 11..4): per-thread scalar at store
        {
            float2 dfix = make_float2(1.f, 0.f);
#pragma unroll
            for (int j = 0; j < 8; j++)
                if ((t >> j) & 1) dfix = cmul(dfix, gm[11 - j][1]);
#pragma unroll
            for (int g = 0; g < 16; g++) st[swzA + (g << 8)] = cmul(dfix, v[g]);
        }
        __syncthreads();

        // --- sweep B: bits 4..7 (wires 7..4), pure real rotations ---
#pragma unroll
        for (int g = 0; g < 16; g++) v[g] = st[baseB ^ ((g << 4) | g)];
#pragma unroll
        for (int k2 = 0; k2 < 4; k2++) {
            int w = 7 - k2;
            float c = gm[w][0].x, s = gm[w][0].y;
            int sft = 1 << k2;
#pragma unroll
            for (int i = 0; i < 16; i++) {
                if (i & sft) continue;
                float2 p0 = v[i], p1 = v[i | sft];
                v[i]       = make_float2(c * p0.x - s * p1.x, c * p0.y - s * p1.y);
                v[i | sft] = make_float2(s * p0.x + c * p1.x, s * p0.y + c * p1.y);
            }
        }
#pragma unroll
        for (int g = 0; g < 16; g++) st[baseB ^ ((g << 4) | g)] = v[g];
        __syncthreads();

        // --- sweep C: bits 0..3 (wires 11..8) + perm + readout ---
#pragma unroll
        for (int g = 0; g < 16; g++) v[g] = st[swzC ^ g];
        __syncthreads();                 // all loads complete before scatter

        if (k < KS - 1) {
            // post-diag folded: diag(1,wpost) * R per wire
#pragma unroll
            for (int k2 = 0; k2 < 4; k2++) {
                int w = 11 - k2;
                float c = gm[w][0].x, s = gm[w][0].y;
                float2 wp = gm[w][2];
                int sft = 1 << k2;
#pragma unroll
                for (int i = 0; i < 16; i++) {
                    if (i & sft) continue;
                    float2 p0 = v[i], p1 = v[i | sft];
                    float ux = s * p0.x + c * p1.x;
                    float uy = s * p0.y + c * p1.y;
                    v[i]       = make_float2(c * p0.x - s * p1.x, c * p0.y - s * p1.y);
                    v[i | sft] = make_float2(wp.x * ux - wp.y * uy,
                                             wp.x * uy + wp.y * ux);
                }
            }
            // post-diag fixed bits 4..11 (wires 7..0): per-thread scalar
            float2 dfp = make_float2(1.f, 0.f);
#pragma unroll
            for (int j = 0; j < 8; j++)
                if ((t >> j) & 1) dfp = cmul(dfp, gm[7 - j][2]);
#pragma unroll
            for (int g = 0; g < 16; g++) v[g] = cmul(dfp, v[g]);
            perm_scatter_readout<true>(v, st, wred, ro[k], t);
        } else {
            // last step: post-diag & scatter skipped (only |amp|^2 needed)
#pragma unroll
            for (int k2 = 0; k2 < 4; k2++) {
                int w = 11 - k2;
                float c = gm[w][0].x, s = gm[w][0].y;
                int sft = 1 << k2;
#pragma unroll
                for (int i = 0; i < 16; i++) {
                    if (i & sft) continue;
                    float2 p0 = v[i], p1 = v[i | sft];
                    v[i]       = make_float2(c * p0.x - s * p1.x, c * p0.y - s * p1.y);
                    v[i | sft] = make_float2(s * p0.x + c * p1.x, s * p0.y + c * p1.y);
                }
            }
            perm_scatter_readout<false>(v, st, wred, ro[k], t);
        }
    }
    __syncthreads();

    // heads + outputs. Layout: step_logits[6,256,8] | step_readouts[6,256,12] | final[256,8]
    if (t < KS * NCLS) {
        int k = t >> 3, c = t & 7;
        float s = hb[c];
#pragma unroll
        for (int j = 0; j < NQ; j++) s += hw[c * NQ + j] * ro[k][j];
        out[(k * BATCH + b) * NCLS + c] = s;
        if (k == KS - 1)
            out[KS * BATCH * NCLS + KS * BATCH * NQ + b * NCLS + c] = s;
    }
    if (t >= 64 && t < 64 + KS * NQ) {
        int u = t - 64;
        int k = u / NQ, j = u % NQ;
        out[KS * BATCH * NCLS + (k * BATCH + b) * NQ + j] = ro[k][j];
    }
}

extern "C" void kernel_launch(void* const* d_in, const int* in_sizes, int n_in,
                              void* d_out, int out_size)
{
    const int*   ids   = (const int*)d_in[0];
    const int*   mask  = (const int*)d_in[1];
    const float* emb   = (const float*)d_in[2];
    const float* pw    = (const float*)d_in[3];
    const float* pb    = (const float*)d_in[4];
    const float* theta = (const float*)d_in[5];
    const float* hw    = (const float*)d_in[6];
    const float* hb    = (const float*)d_in[7];
    float* out = (float*)d_out;

    encoder_kernel<<<BATCH, 256>>>(ids, mask, emb, pw, pb);
    quantum_kernel<<<BATCH, 256>>>(theta, hw, hb, out);
}

// round 9
// speedup vs baseline: 1.8196x; 1.1160x over previous
#include <cuda_runtime.h>
#include <math.h>

#define NQ    12
#define DIM   4096
#define KS    6
#define BATCH 256
#define SEQ   128
#define DEMB  512
#define NCLS  8

// swizzle: XOR low nibble with next nibble (GF(2)-linear)
__device__ __host__ constexpr int swzc(int i) { return i ^ ((i >> 4) & 0xF); }

// CNOT-ring composition: bits 0..10 = suffix parity, bit 11 = parity(bits 0..10)
__device__ __host__ constexpr int permTc(int x) {
    int p = x ^ (x >> 1);
    p ^= p >> 2;
    p ^= p >> 4;
    p ^= p >> 8;
    return (p & 0x7FF) | (((p ^ (x >> 11)) & 1) << 11);
}

__device__ __forceinline__ float2 cmul(float2 a, float2 b) {
    return make_float2(a.x * b.x - a.y * b.y, a.x * b.y + a.y * b.x);
}

// CNOT-ring permuted scatter (optional) + Z readout for a sweep-C register
// group (thread t owns idx = t*16+g). Diagonal phases never change |amp|^2.
// Contains __syncthreads (which also orders the scatter stores against the
// next step's sweep-A loads — no extra loop-top barrier needed).
template <bool STORE>
__device__ __forceinline__ void perm_scatter_readout(
    float2 v[16], float2* st, float (*wred)[NQ], float* ro_k, int t)
{
    const int ybase = permTc(t << 4);          // once per thread
    const int sybase = swzc(ybase);            // swizzled scatter base

    float acc0 = 0.f, acc1 = 0.f, acc2 = 0.f, acc3 = 0.f, acc11 = 0.f, ptot = 0.f;
#pragma unroll
    for (int g = 0; g < 16; g++) {
        const int PT = permTc(g);              // compile-time
        const int SPT = swzc(PT);              // compile-time
        if (STORE) st[sybase ^ SPT] = v[g];
        float p = v[g].x * v[g].x + v[g].y * v[g].y;
        ptot += p;
        acc0  += (PT & 1)        ? -p : p;     // folds to FADD/FSUB
        acc1  += ((PT >> 1) & 1) ? -p : p;
        acc2  += ((PT >> 2) & 1) ? -p : p;
        acc3  += ((PT >> 3) & 1) ? -p : p;
        acc11 += ((PT >> 11) & 1)? -p : p;
    }

    float zb[NQ];
    zb[0]  = (ybase & 1)         ? -acc0  : acc0;
    zb[1]  = ((ybase >> 1) & 1)  ? -acc1  : acc1;
    zb[2]  = ((ybase >> 2) & 1)  ? -acc2  : acc2;
    zb[3]  = ((ybase >> 3) & 1)  ? -acc3  : acc3;
    zb[11] = ((ybase >> 11) & 1) ? -acc11 : acc11;
#pragma unroll
    for (int bb = 4; bb < 11; bb++)
        zb[bb] = ((ybase >> bb) & 1) ? -ptot : ptot;

#pragma unroll
    for (int bb = 0; bb < NQ; bb++) {
#pragma unroll
        for (int off = 16; off; off >>= 1)
            zb[bb] += __shfl_down_sync(0xffffffffu, zb[bb], off);
    }
    int w = t >> 5, l = t & 31;
    if (l == 0) {
#pragma unroll
        for (int bb = 0; bb < NQ; bb++) wred[w][bb] = zb[bb];
    }
    __syncthreads();
    if (t < NQ) {
        float s = 0.f;
#pragma unroll
        for (int w2 = 0; w2 < 8; w2++) s += wred[w2][11 - t]; // wire t = bit 11-t
        ro_k[t] = s;
    }
}

// ---------------------------------------------------------------------------
// Fully fused, 1 sample per CTA, 256 threads, grid=256 (2 CTAs/SM).
// Encoder phase -> per-CTA x -> D*R*D decomposed quantum sim -> heads.
// No cross-CTA dependency: early-finishing CTAs start simulating while
// stragglers' encoder DRAM latency overlaps their compute.
// ---------------------------------------------------------------------------
__global__ void __launch_bounds__(256, 2) fused_kernel(
    const int* __restrict__ ids, const int* __restrict__ mask,
    const float* __restrict__ emb, const float* __restrict__ pw,
    const float* __restrict__ pb, const float* __restrict__ theta,
    const float* __restrict__ hw, const float* __restrict__ hb,
    float* __restrict__ out)
{
    __shared__ float2 st[DIM];            // 32 KB state, swizzled addressing
    __shared__ float2 gp[KS][NQ][4];      // [0]=(c,s) [1]=wpre [2]=wpost [3]=s*wpost
    __shared__ float2 plo[16];            // step-1 low-bit partial products
    __shared__ float  ro[KS][NQ];
    __shared__ float  wred[8][NQ];
    __shared__ float  xs[NQ];

    int b = blockIdx.x, t = threadIdx.x;

    // ===================== encoder phase (scratch aliases st) ================
    {
        int*   sid  = (int*)st;                  // [SEQ]
        float* smk  = (float*)st + SEQ;          // [SEQ]
        float* ered = (float*)st + 2 * SEQ;      // [8][13]
        if (t < SEQ) {
            sid[t] = ids[b * SEQ + t];
            smk[t] = (float)mask[b * SEQ + t];
        }
        __syncthreads();

        int d = t & 127, sh = t >> 7;            // dim-chunk, seq-half
        float a0 = 0.f, a1 = 0.f, a2 = 0.f, a3 = 0.f, cnt = 0.f;
#pragma unroll 4
        for (int s = sh * 64; s < sh * 64 + 64; s++) {
            float m = smk[s];
            cnt += m;
            const float4 e = __ldg((const float4*)(emb + (size_t)sid[s] * DEMB + d * 4));
            a0 += m * e.x; a1 += m * e.y; a2 += m * e.z; a3 += m * e.w;
        }

        float z[NQ + 1];
#pragma unroll
        for (int q = 0; q < NQ; q++) {
            const float4 w = __ldg((const float4*)(pw + q * DEMB + d * 4));
            z[q] = a0 * w.x + a1 * w.y + a2 * w.z + a3 * w.w;
        }
        z[NQ] = cnt;
#pragma unroll
        for (int q = 0; q <= NQ; q++) {
#pragma unroll
            for (int off = 16; off; off >>= 1)
                z[q] += __shfl_down_sync(0xffffffffu, z[q], off);
        }
        __syncthreads();                         // sid/smk reads complete
        int w = t >> 5, l = t & 31;
        if (l == 0) {
#pragma unroll
            for (int q = 0; q <= NQ; q++) ered[w * 13 + q] = z[q];
        }
        __syncthreads();
        if (t < NQ) {
            float s = 0.f, c = 0.f;
#pragma unroll
            for (int w2 = 0; w2 < 8; w2++) { s += ered[w2 * 13 + t]; c += ered[w2 * 13 + NQ]; }
            float inv = 1.0f / fmaxf(c * (1.0f / 128.0f), 1.0f);
            xs[t] = tanhf(s * inv + pb[t]) * 3.14159265358979f;
        }
        __syncthreads();
    }

    // ===================== gate precompute (D*R*D), 72 threads ===============
    if (t < KS * NQ) {
        int k = t / NQ, q = t % NQ;
        float cy, sy;  sincosf(0.5f * xs[q], &sy, &cy);
        const float* th = theta + (k * NQ + q) * 3;
        float phi = th[0], tha = th[1], om = th[2];
        float ct, stt; sincosf(0.5f * tha, &stt, &ct);
        float ca, sa;  sincosf(0.5f * (phi + om), &sa, &ca); // ep = (ca,-sa)
        float cb, sb;  sincosf(0.5f * (phi - om), &sb, &cb); // em = (cb, sb)
        float r00 = ct * cy, r01 = ct * sy, r10 = stt * cy, r11 = stt * sy;
        float2 G00 = make_float2( ca * r00 - cb * r11, -sa * r00 - sb * r11);
        float2 G01 = make_float2(-ca * r01 - cb * r10,  sa * r01 - sb * r10);
        float2 G10 = make_float2( cb * r10 + ca * r01, -sb * r10 + sa * r01);

        float c = sqrtf(G00.x * G00.x + G00.y * G00.y);
        float s = sqrtf(G10.x * G10.x + G10.y * G10.y);
        float2 cj = make_float2(G00.x, -G00.y);
        float2 wpre = cmul(make_float2(-G01.x, -G01.y), cj);
        float n1 = wpre.x * wpre.x + wpre.y * wpre.y;
        if (n1 > 1e-24f) { float r = rsqrtf(n1); wpre.x *= r; wpre.y *= r; }
        else wpre = make_float2(1.f, 0.f);
        float2 wpost = cmul(G10, cj);
        float n2 = wpost.x * wpost.x + wpost.y * wpost.y;
        if (n2 > 1e-24f) { float r = rsqrtf(n2); wpost.x *= r; wpost.y *= r; }
        else wpost = make_float2(1.f, 0.f);

        gp[k][q][0] = make_float2(c, s);
        gp[k][q][1] = wpre;
        gp[k][q][2] = wpost;
        gp[k][q][3] = make_float2(s * wpost.x, s * wpost.y);  // col0 bit-1 entry
    }
    __syncthreads();
    // step-1 low-bit table: idx bits 0..3 -> wires 11..8; col0 = (c, s*wpost)
    if (t < 16) {
        float2 p = ((t     ) & 1) ? gp[0][11][3] : make_float2(gp[0][11][0].x, 0.f);
        p = cmul(p, ((t >> 1) & 1) ? gp[0][10][3] : make_float2(gp[0][10][0].x, 0.f));
        p = cmul(p, ((t >> 2) & 1) ? gp[0][ 9][3] : make_float2(gp[0][ 9][0].x, 0.f));
        p = cmul(p, ((t >> 3) & 1) ? gp[0][ 8][3] : make_float2(gp[0][ 8][0].x, 0.f));
        plo[t] = p;
    }
    __syncthreads();

    // ===== step 1 (analytic product state; amp(idx) = P_hi(t) * plo[g]) =====
    {
        float2 pt = (t & 1) ? gp[0][7][3] : make_float2(gp[0][7][0].x, 0.f);
#pragma unroll
        for (int j = 1; j < 8; j++)
            pt = cmul(pt, ((t >> j) & 1) ? gp[0][7 - j][3]
                                         : make_float2(gp[0][7 - j][0].x, 0.f));
        float2 v[16];
#pragma unroll
        for (int g = 0; g < 16; g++) v[g] = cmul(pt, plo[g]);
        perm_scatter_readout<true>(v, st, wred, ro[0], t);
    }

    // per-thread swizzled bases (step-invariant)
    const int swzA  = swzc(t);                       // sweep A: + (g<<8)
    const int baseB = (t & 15) | ((t >> 4) << 8);    // sweep B: ^ ((g<<4)|g)
    const int swzC  = (t << 4) | (t & 15);           // sweep C: ^ g

    // ===== steps 2..6 (no loop-top barrier: readout's wred barrier orders
    //       the scatter stores against these sweep-A loads) =====
    for (int k = 1; k < KS; k++) {
        const float2 (*gm)[4] = gp[k];
        float2 v[16];

        // --- sweep A: bits 8..11 (wires 3..0), pre-diag folded: R * diag(1,wpre)
#pragma unroll
        for (int g = 0; g < 16; g++) v[g] = st[swzA + (g << 8)];
#pragma unroll
        for (int k2 = 0; k2 < 4; k2++) {
            int w = 3 - k2;
            float c = gm[w][0].x, s = gm[w][0].y;
            float2 wp = gm[w][1];
            float2 sw = make_float2(s * wp.x, s * wp.y);
            float2 cw = make_float2(c * wp.x, c * wp.y);
            int sft = 1 << k2;
#pragma unroll
            for (int i = 0; i < 16; i++) {
                if (i & sft) continue;
                float2 p0 = v[i], p1 = v[i | sft];
                float ax = sw.x * p1.x - sw.y * p1.y;
                float ay = sw.x * p1.y + sw.y * p1.x;
                float bx = cw.x * p1.x - cw.y * p1.y;
                float by = cw.x * p1.y + cw.y * p1.x;
                v[i]       = make_float2(c * p0.x - ax, c * p0.y - ay);
                v[i | sft] = make_float2(s * p0.x + bx, s * p0.y + by);
            }
        }
        // pre-diag fixed bits 0..7 (wires 11..4): per-thread scalar at store
        {
            float2 dfix = make_float2(1.f, 0.f);
#pragma unroll
            for (int j = 0; j < 8; j++)
                if ((t >> j) & 1) dfix = cmul(dfix, gm[11 - j][1]);
#pragma unroll
            for (int g = 0; g < 16; g++) st[swzA + (g << 8)] = cmul(dfix, v[g]);
        }
        __syncthreads();

        // --- sweep B: bits 4..7 (wires 7..4), pure real rotations ---
#pragma unroll
        for (int g = 0; g < 16; g++) v[g] = st[baseB ^ ((g << 4) | g)];
#pragma unroll
        for (int k2 = 0; k2 < 4; k2++) {
            int w = 7 - k2;
            float c = gm[w][0].x, s = gm[w][0].y;
            int sft = 1 << k2;
#pragma unroll
            for (int i = 0; i < 16; i++) {
                if (i & sft) continue;
                float2 p0 = v[i], p1 = v[i | sft];
                v[i]       = make_float2(c * p0.x - s * p1.x, c * p0.y - s * p1.y);
                v[i | sft] = make_float2(s * p0.x + c * p1.x, s * p0.y + c * p1.y);
            }
        }
#pragma unroll
        for (int g = 0; g < 16; g++) st[baseB ^ ((g << 4) | g)] = v[g];
        __syncthreads();

        // --- sweep C: bits 0..3 (wires 11..8) + perm + readout ---
#pragma unroll
        for (int g = 0; g < 16; g++) v[g] = st[swzC ^ g];
        __syncthreads();                 // all loads complete before scatter

        if (k < KS - 1) {
            // post-diag folded: diag(1,wpost) * R per wire
#pragma unroll
            for (int k2 = 0; k2 < 4; k2++) {
                int w = 11 - k2;
                float c = gm[w][0].x, s = gm[w][0].y;
                float2 wp = gm[w][2];
                int sft = 1 << k2;
#pragma unroll
                for (int i = 0; i < 16; i++) {
                    if (i & sft) continue;
                    float2 p0 = v[i], p1 = v[i | sft];
                    float ux = s * p0.x + c * p1.x;
                    float uy = s * p0.y + c * p1.y;
                    v[i]       = make_float2(c * p0.x - s * p1.x, c * p0.y - s * p1.y);
                    v[i | sft] = make_float2(wp.x * ux - wp.y * uy,
                                             wp.x * uy + wp.y * ux);
                }
            }
            // post-diag fixed bits 4..11 (wires 7..0): per-thread scalar
            float2 dfp = make_float2(1.f, 0.f);
#pragma unroll
            for (int j = 0; j < 8; j++)
                if ((t >> j) & 1) dfp = cmul(dfp, gm[7 - j][2]);
#pragma unroll
            for (int g = 0; g < 16; g++) v[g] = cmul(dfp, v[g]);
            perm_scatter_readout<true>(v, st, wred, ro[k], t);
        } else {
            // last step: post-diag & scatter skipped (only |amp|^2 needed)
#pragma unroll
            for (int k2 = 0; k2 < 4; k2++) {
                int w = 11 - k2;
                float c = gm[w][0].x, s = gm[w][0].y;
                int sft = 1 << k2;
#pragma unroll
                for (int i = 0; i < 16; i++) {
                    if (i & sft) continue;
                    float2 p0 = v[i], p1 = v[i | sft];
                    v[i]       = make_float2(c * p0.x - s * p1.x, c * p0.y - s * p1.y);
                    v[i | sft] = make_float2(s * p0.x + c * p1.x, s * p0.y + c * p1.y);
                }
            }
            perm_scatter_readout<false>(v, st, wred, ro[k], t);
        }
    }
    __syncthreads();

    // heads + outputs. Layout: step_logits[6,256,8] | step_readouts[6,256,12] | final[256,8]
    if (t < KS * NCLS) {
        int k = t >> 3, c = t & 7;
        float s = hb[c];
#pragma unroll
        for (int j = 0; j < NQ; j++) s += hw[c * NQ + j] * ro[k][j];
        out[(k * BATCH + b) * NCLS + c] = s;
        if (k == KS - 1)
            out[KS * BATCH * NCLS + KS * BATCH * NQ + b * NCLS + c] = s;
    }
    if (t >= 64 && t < 64 + KS * NQ) {
        int u = t - 64;
        int k = u / NQ, j = u % NQ;
        out[KS * BATCH * NCLS + (k * BATCH + b) * NQ + j] = ro[k][j];
    }
}

extern "C" void kernel_launch(void* const* d_in, const int* in_sizes, int n_in,
                              void* d_out, int out_size)
{
    const int*   ids   = (const int*)d_in[0];
    const int*   mask  = (const int*)d_in[1];
    const float* emb   = (const float*)d_in[2];
    const float* pw    = (const float*)d_in[3];
    const float* pb    = (const float*)d_in[4];
    const float* theta = (const float*)d_in[5];
    const float* hw    = (const float*)d_in[6];
    const float* hb    = (const float*)d_in[7];
    float* out = (float*)d_out;

    fused_kernel<<<BATCH, 256>>>(ids, mask, emb, pw, pb, theta, hw, hb, out);
}

// round 11
// speedup vs baseline: 1.8952x; 1.0415x over previous
#include <cuda_runtime.h>
#include <math.h>

#define NQ    12
#define DIM   4096
#define KS    6
#define BATCH 256
#define SEQ   128
#define DEMB  512
#define NCLS  8

// swizzle: XOR low nibble with next nibble (GF(2)-linear)
__device__ __host__ constexpr int swzc(int i) { return i ^ ((i >> 4) & 0xF); }

// CNOT-ring composition: bits 0..10 = suffix parity, bit 11 = parity(bits 0..10)
__device__ __host__ constexpr int permTc(int x) {
    int p = x ^ (x >> 1);
    p ^= p >> 2;
    p ^= p >> 4;
    p ^= p >> 8;
    return (p & 0x7FF) | (((p ^ (x >> 11)) & 1) << 11);
}

__device__ __forceinline__ float2 cmul(float2 a, float2 b) {
    return make_float2(a.x * b.x - a.y * b.y, a.x * b.y + a.y * b.x);
}

// CNOT-ring permuted scatter (optional) + Z readout for a sweep-C register
// group (thread t owns idx = t*16+g). Diagonal phases never change |amp|^2.
// Warp reduction uses a split-exchange scheme: 18 shuffles for 12 values
// (vs 60 for 12 independent trees). Contains __syncthreads.
template <bool STORE>
__device__ __forceinline__ void perm_scatter_readout(
    float2 v[16], float2* st, float (*wred)[NQ], float* ro_k, int t)
{
    const int ybase = permTc(t << 4);          // once per thread
    const int sybase = swzc(ybase);            // swizzled scatter base

    float acc0 = 0.f, acc1 = 0.f, acc2 = 0.f, acc3 = 0.f, acc11 = 0.f, ptot = 0.f;
#pragma unroll
    for (int g = 0; g < 16; g++) {
        const int PT = permTc(g);              // compile-time
        const int SPT = swzc(PT);              // compile-time
        if (STORE) st[sybase ^ SPT] = v[g];
        float p = v[g].x * v[g].x + v[g].y * v[g].y;
        ptot += p;
        acc0  += (PT & 1)        ? -p : p;     // folds to FADD/FSUB
        acc1  += ((PT >> 1) & 1) ? -p : p;
        acc2  += ((PT >> 2) & 1) ? -p : p;
        acc3  += ((PT >> 3) & 1) ? -p : p;
        acc11 += ((PT >> 11) & 1)? -p : p;
    }

    float zb[NQ];
    zb[0]  = (ybase & 1)         ? -acc0  : acc0;
    zb[1]  = ((ybase >> 1) & 1)  ? -acc1  : acc1;
    zb[2]  = ((ybase >> 2) & 1)  ? -acc2  : acc2;
    zb[3]  = ((ybase >> 3) & 1)  ? -acc3  : acc3;
    zb[11] = ((ybase >> 11) & 1) ? -acc11 : acc11;
#pragma unroll
    for (int bb = 4; bb < 11; bb++)
        zb[bb] = ((ybase >> bb) & 1) ? -ptot : ptot;

    // --- split-exchange warp reduction: 12 -> 6 -> 3 values ---
    const int lane = t & 31;
    const bool hi16 = (lane & 16) != 0;
    const bool hi8  = (lane & 8) != 0;
    float s6[6];
#pragma unroll
    for (int j = 0; j < 6; j++) {              // level xor=16: keep 6, send 6
        float snd = hi16 ? zb[j] : zb[j + 6];
        float kp  = hi16 ? zb[j + 6] : zb[j];
        s6[j] = kp + __shfl_xor_sync(0xffffffffu, snd, 16);
    }
    float u3[3];
#pragma unroll
    for (int j = 0; j < 3; j++) {              // level xor=8: keep 3, send 3
        float snd = hi8 ? s6[j] : s6[j + 3];
        float kp  = hi8 ? s6[j + 3] : s6[j];
        u3[j] = kp + __shfl_xor_sync(0xffffffffu, snd, 8);
    }
#pragma unroll
    for (int j = 0; j < 3; j++) {              // 3 standard levels on 3 values
        u3[j] += __shfl_xor_sync(0xffffffffu, u3[j], 4);
        u3[j] += __shfl_xor_sync(0xffffffffu, u3[j], 2);
        u3[j] += __shfl_xor_sync(0xffffffffu, u3[j], 1);
    }
    // lane 0 -> values 0..2, lane 8 -> 3..5, lane 16 -> 6..8, lane 24 -> 9..11
    int w = t >> 5;
    if ((lane & 7) == 0) {
        int base = (lane >> 3) * 3;
#pragma unroll
        for (int j = 0; j < 3; j++) wred[w][base + j] = u3[j];
    }
    __syncthreads();
    if (t < NQ) {
        float s = 0.f;
#pragma unroll
        for (int w2 = 0; w2 < 8; w2++) s += wred[w2][11 - t]; // wire t = bit 11-t
        ro_k[t] = s;
    }
}

// ---------------------------------------------------------------------------
// Fully fused, 1 sample per CTA, 256 threads, grid=256 (2 CTAs/SM).
// Encoder -> D*R*D decomposed quantum sim (diag fixups via XOR-split SMEM
// tables) -> heads. No cross-CTA dependency.
// ---------------------------------------------------------------------------
__global__ void __launch_bounds__(256, 2) fused_kernel(
    const int* __restrict__ ids, const int* __restrict__ mask,
    const float* __restrict__ emb, const float* __restrict__ pw,
    const float* __restrict__ pb, const float* __restrict__ theta,
    const float* __restrict__ hw, const float* __restrict__ hb,
    float* __restrict__ out)
{
    __shared__ float2 st[DIM];            // 32 KB state, swizzled addressing
    __shared__ float2 gp[KS][NQ][4];      // [0]=(c,s) [1]=wpre [2]=wpost [3]=s*wpost
    __shared__ float2 plo[16];            // step-1 low-bit partial products
    __shared__ float2 dpre1[KS][16], dpre2[KS][16];  // dfix = dpre1[t&15]*dpre2[t>>4]
    __shared__ float2 dpo1[KS][16],  dpo2[KS][16];   // dfp  = dpo1[t&15]*dpo2[t>>4]
    __shared__ float  ro[KS][NQ];
    __shared__ float  wred[8][NQ];
    __shared__ float  xs[NQ];

    int b = blockIdx.x, t = threadIdx.x;

    // ===================== encoder phase (scratch aliases st) ================
    {
        int*   sid  = (int*)st;                  // [SEQ]
        float* smk  = (float*)st + SEQ;          // [SEQ]
        float* ered = (float*)st + 2 * SEQ;      // [8][13]
        if (t < SEQ) {
            sid[t] = ids[b * SEQ + t];
            smk[t] = (float)mask[b * SEQ + t];
        }
        __syncthreads();

        int d = t & 127, sh = t >> 7;            // dim-chunk, seq-half
        float a0 = 0.f, a1 = 0.f, a2 = 0.f, a3 = 0.f, cnt = 0.f;
#pragma unroll 4
        for (int s = sh * 64; s < sh * 64 + 64; s++) {
            float m = smk[s];
            cnt += m;
            const float4 e = __ldg((const float4*)(emb + (size_t)sid[s] * DEMB + d * 4));
            a0 += m * e.x; a1 += m * e.y; a2 += m * e.z; a3 += m * e.w;
        }

        float z[NQ + 1];
#pragma unroll
        for (int q = 0; q < NQ; q++) {
            const float4 w = __ldg((const float4*)(pw + q * DEMB + d * 4));
            z[q] = a0 * w.x + a1 * w.y + a2 * w.z + a3 * w.w;
        }
        z[NQ] = cnt;
#pragma unroll
        for (int q = 0; q <= NQ; q++) {
#pragma unroll
            for (int off = 16; off; off >>= 1)
                z[q] += __shfl_down_sync(0xffffffffu, z[q], off);
        }
        __syncthreads();                         // sid/smk reads complete
        int w = t >> 5, l = t & 31;
        if (l == 0) {
#pragma unroll
            for (int q = 0; q <= NQ; q++) ered[w * 13 + q] = z[q];
        }
        __syncthreads();
        if (t < NQ) {
            float s = 0.f, c = 0.f;
#pragma unroll
            for (int w2 = 0; w2 < 8; w2++) { s += ered[w2 * 13 + t]; c += ered[w2 * 13 + NQ]; }
            float inv = 1.0f / fmaxf(c * (1.0f / 128.0f), 1.0f);
            xs[t] = tanhf(s * inv + pb[t]) * 3.14159265358979f;
        }
        __syncthreads();
    }

    // ===================== gate precompute (D*R*D), 72 threads ===============
    if (t < KS * NQ) {
        int k = t / NQ, q = t % NQ;
        float cy, sy;  sincosf(0.5f * xs[q], &sy, &cy);
        const float* th = theta + (k * NQ + q) * 3;
        float phi = th[0], tha = th[1], om = th[2];
        float ct, stt; sincosf(0.5f * tha, &stt, &ct);
        float ca, sa;  sincosf(0.5f * (phi + om), &sa, &ca); // ep = (ca,-sa)
        float cb, sb;  sincosf(0.5f * (phi - om), &sb, &cb); // em = (cb, sb)
        float r00 = ct * cy, r01 = ct * sy, r10 = stt * cy, r11 = stt * sy;
        float2 G00 = make_float2( ca * r00 - cb * r11, -sa * r00 - sb * r11);
        float2 G01 = make_float2(-ca * r01 - cb * r10,  sa * r01 - sb * r10);
        float2 G10 = make_float2( cb * r10 + ca * r01, -sb * r10 + sa * r01);

        float c = sqrtf(G00.x * G00.x + G00.y * G00.y);
        float s = sqrtf(G10.x * G10.x + G10.y * G10.y);
        float2 cj = make_float2(G00.x, -G00.y);
        float2 wpre = cmul(make_float2(-G01.x, -G01.y), cj);
        float n1 = wpre.x * wpre.x + wpre.y * wpre.y;
        if (n1 > 1e-24f) { float r = rsqrtf(n1); wpre.x *= r; wpre.y *= r; }
        else wpre = make_float2(1.f, 0.f);
        float2 wpost = cmul(G10, cj);
        float n2 = wpost.x * wpost.x + wpost.y * wpost.y;
        if (n2 > 1e-24f) { float r = rsqrtf(n2); wpost.x *= r; wpost.y *= r; }
        else wpost = make_float2(1.f, 0.f);

        gp[k][q][0] = make_float2(c, s);
        gp[k][q][1] = wpre;
        gp[k][q][2] = wpost;
        gp[k][q][3] = make_float2(s * wpost.x, s * wpost.y);  // col0 bit-1 entry
    }
    __syncthreads();

    // step-1 low-bit table: idx bits 0..3 -> wires 11..8; col0 = (c, s*wpost)
    if (t < 16) {
        float2 p = ((t     ) & 1) ? gp[0][11][3] : make_float2(gp[0][11][0].x, 0.f);
        p = cmul(p, ((t >> 1) & 1) ? gp[0][10][3] : make_float2(gp[0][10][0].x, 0.f));
        p = cmul(p, ((t >> 2) & 1) ? gp[0][ 9][3] : make_float2(gp[0][ 9][0].x, 0.f));
        p = cmul(p, ((t >> 3) & 1) ? gp[0][ 8][3] : make_float2(gp[0][ 8][0].x, 0.f));
        plo[t] = p;
    }
    // diag-fixup tables for steps 1..5 (XOR-split of the 8-bit products):
    //   dpre1[m] = prod_{j bit of m} wpre(wire 11-j), dpre2: wire 7-j
    //   dpo1[m]  = prod_{j bit of m} wpost(wire 7-j), dpo2:  wire 3-j
    {
        int idx = t;                             // entries 0..319, 256 threads
#pragma unroll
        for (int pass = 0; pass < 2; pass++, idx += 256) {
            if (idx < (KS - 1) * 64) {
                int k = 1 + idx / 64, r = idx & 63, tbl = r >> 4, m = r & 15;
                int w0  = (tbl == 0) ? 11 : (tbl == 3) ? 3 : 7;
                int col = (tbl < 2) ? 1 : 2;
                float2 e = make_float2(1.f, 0.f);
#pragma unroll
                for (int j = 0; j < 4; j++)
                    if ((m >> j) & 1) e = cmul(e, gp[k][w0 - j][col]);
                float2* dst = (tbl == 0) ? dpre1[k] : (tbl == 1) ? dpre2[k]
                            : (tbl == 2) ? dpo1[k]  : dpo2[k];
                dst[m] = e;
            }
        }
    }
    __syncthreads();

    // ===== step 1 (analytic product state; amp(idx) = P_hi(t) * plo[g]) =====
    {
        float2 pt = (t & 1) ? gp[0][7][3] : make_float2(gp[0][7][0].x, 0.f);
#pragma unroll
        for (int j = 1; j < 8; j++)
            pt = cmul(pt, ((t >> j) & 1) ? gp[0][7 - j][3]
                                         : make_float2(gp[0][7 - j][0].x, 0.f));
        float2 v[16];
#pragma unroll
        for (int g = 0; g < 16; g++) v[g] = cmul(pt, plo[g]);
        perm_scatter_readout<true>(v, st, wred, ro[0], t);
    }

    // per-thread swizzled bases (step-invariant)
    const int swzA  = swzc(t);                       // sweep A: + (g<<8)
    const int baseB = (t & 15) | ((t >> 4) << 8);    // sweep B: ^ ((g<<4)|g)
    const int swzC  = (t << 4) | (t & 15);           // sweep C: ^ g
    const int tlo = t & 15, thi = (t >> 4) & 15;

    // ===== steps 2..6 (no loop-top barrier: readout's wred barrier orders
    //       the scatter stores against these sweep-A loads) =====
    for (int k = 1; k < KS; k++) {
        const float2 (*gm)[4] = gp[k];
        float2 v[16];

        // --- sweep A: bits 8..11 (wires 3..0), pre-diag folded: R * diag(1,wpre)
#pragma unroll
        for (int g = 0; g < 16; g++) v[g] = st[swzA + (g << 8)];
#pragma unroll
        for (int k2 = 0; k2 < 4; k2++) {
            int w = 3 - k2;
            float c = gm[w][0].x, s = gm[w][0].y;
            float2 wp = gm[w][1];
            float2 sw = make_float2(s * wp.x, s * wp.y);
            float2 cw = make_float2(c * wp.x, c * wp.y);
            int sft = 1 << k2;
#pragma unroll
            for (int i = 0; i < 16; i++) {
                if (i & sft) continue;
                float2 p0 = v[i], p1 = v[i | sft];
                float ax = sw.x * p1.x - sw.y * p1.y;
                float ay = sw.x * p1.y + sw.y * p1.x;
                float bx = cw.x * p1.x - cw.y * p1.y;
                float by = cw.x * p1.y + cw.y * p1.x;
                v[i]       = make_float2(c * p0.x - ax, c * p0.y - ay);
                v[i | sft] = make_float2(s * p0.x + bx, s * p0.y + by);
            }
        }
        // pre-diag fixed bits 0..7 (wires 11..4): table lookup, 1 cmul
        {
            float2 dfix = cmul(dpre1[k][tlo], dpre2[k][thi]);
#pragma unroll
            for (int g = 0; g < 16; g++) st[swzA + (g << 8)] = cmul(dfix, v[g]);
        }
        __syncthreads();

        // --- sweep B: bits 4..7 (wires 7..4), pure real rotations ---
#pragma unroll
        for (int g = 0; g < 16; g++) v[g] = st[baseB ^ ((g << 4) | g)];
#pragma unroll
        for (int k2 = 0; k2 < 4; k2++) {
            int w = 7 - k2;
            float c = gm[w][0].x, s = gm[w][0].y;
            int sft = 1 << k2;
#pragma unroll
            for (int i = 0; i < 16; i++) {
                if (i & sft) continue;
                float2 p0 = v[i], p1 = v[i | sft];
                v[i]       = make_float2(c * p0.x - s * p1.x, c * p0.y - s * p1.y);
                v[i | sft] = make_float2(s * p0.x + c * p1.x, s * p0.y + c * p1.y);
            }
        }
#pragma unroll
        for (int g = 0; g < 16; g++) st[baseB ^ ((g << 4) | g)] = v[g];
        __syncthreads();

        // --- sweep C: bits 0..3 (wires 11..8) + perm + readout ---
#pragma unroll
        for (int g = 0; g < 16; g++) v[g] = st[swzC ^ g];
        __syncthreads();                 // all loads complete before scatter

        if (k < KS - 1) {
            // post-diag folded: diag(1,wpost) * R per wire
#pragma unroll
            for (int k2 = 0; k2 < 4; k2++) {
                int w = 11 - k2;
                float c = gm[w][0].x, s = gm[w][0].y;
                float2 wp = gm[w][2];
                int sft = 1 << k2;
#pragma unroll
                for (int i = 0; i < 16; i++) {
                    if (i & sft) continue;
                    float2 p0 = v[i], p1 = v[i | sft];
                    float ux = s * p0.x + c * p1.x;
                    float uy = s * p0.y + c * p1.y;
                    v[i]       = make_float2(c * p0.x - s * p1.x, c * p0.y - s * p1.y);
                    v[i | sft] = make_float2(wp.x * ux - wp.y * uy,
                                             wp.x * uy + wp.y * ux);
                }
            }
            // post-diag fixed bits 4..11 (wires 7..0): table lookup, 1 cmul
            float2 dfp = cmul(dpo1[k][tlo], dpo2[k][thi]);
#pragma unroll
            for (int g = 0; g < 16; g++) v[g] = cmul(dfp, v[g]);
            perm_scatter_readout<true>(v, st, wred, ro[k], t);
        } else {
            // last step: post-diag & scatter skipped (only |amp|^2 needed)
#pragma unroll
            for (int k2 = 0; k2 < 4; k2++) {
                int w = 11 - k2;
                float c = gm[w][0].x, s = gm[w][0].y;
                int sft = 1 << k2;
#pragma unroll
                for (int i = 0; i < 16; i++) {
                    if (i & sft) continue;
                    float2 p0 = v[i], p1 = v[i | sft];
                    v[i]       = make_float2(c * p0.x - s * p1.x, c * p0.y - s * p1.y);
                    v[i | sft] = make_float2(s * p0.x + c * p1.x, s * p0.y + c * p1.y);
                }
            }
            perm_scatter_readout<false>(v, st, wred, ro[k], t);
        }
    }
    __syncthreads();

    // heads + outputs. Layout: step_logits[6,256,8] | step_readouts[6,256,12] | final[256,8]
    if (t < KS * NCLS) {
        int k = t >> 3, c = t & 7;
        float s = hb[c];
#pragma unroll
        for (int j = 0; j < NQ; j++) s += hw[c * NQ + j] * ro[k][j];
        out[(k * BATCH + b) * NCLS + c] = s;
        if (k == KS - 1)
            out[KS * BATCH * NCLS + KS * BATCH * NQ + b * NCLS + c] = s;
    }
    if (t >= 64 && t < 64 + KS * NQ) {
        int u = t - 64;
        int k = u / NQ, j = u % NQ;
        out[KS * BATCH * NCLS + (k * BATCH + b) * NQ + j] = ro[k][j];
    }
}

extern "C" void kernel_launch(void* const* d_in, const int* in_sizes, int n_in,
                              void* d_out, int out_size)
{
    const int*   ids   = (const int*)d_in[0];
    const int*   mask  = (const int*)d_in[1];
    const float* emb   = (const float*)d_in[2];
    const float* pw    = (const float*)d_in[3];
    const float* pb    = (const float*)d_in[4];
    const float* theta = (const float*)d_in[5];
    const float* hw    = (const float*)d_in[6];
    const float* hb    = (const float*)d_in[7];
    float* out = (float*)d_out;

    fused_kernel<<<BATCH, 256>>>(ids, mask, emb, pw, pb, theta, hw, hb, out);
}